// round 12
// baseline (speedup 1.0000x reference)
#include <cuda_runtime.h>
#include <cuda_bf16.h>
#include <math.h>
#include <stdint.h>

// ---------------------------------------------------------------------------
// ConvTokenEmbedder: char CNN + highway x2 + projection
// Round 12: gemm_big 512 threads + BK=64 / 3-stage (96 iters, half the
//           barrier count of round 11). Rest = round-11 (3006us) verbatim.
// ---------------------------------------------------------------------------

#define NTOK   4096
#define NFILT  2048
#define PROJ   512
#define MAXC   50
#define CDIM   16
#define KDIM   2048

typedef unsigned long long u64;

// Scratch
__device__ float g_h[NTOK * NFILT];
__device__ float g_p[NTOK * 2 * NFILT];
__device__ float g_wt[197120];
__device__ __nv_bfloat16 g_hhi[NTOK * NFILT];
__device__ __nv_bfloat16 g_hlo[NTOK * NFILT];
__device__ __nv_bfloat16 g_w0hi[2 * NFILT * NFILT];
__device__ __nv_bfloat16 g_w0lo[2 * NFILT * NFILT];
__device__ __nv_bfloat16 g_w1hi[2 * NFILT * NFILT];
__device__ __nv_bfloat16 g_w1lo[2 * NFILT * NFILT];
__device__ __nv_bfloat16 g_wphi[PROJ * NFILT];
__device__ __nv_bfloat16 g_wplo[PROJ * NFILT];

#define WT_O0 0
#define WT_O1 512
#define WT_O2 1536
#define WT_O3 4608
#define WT_O4 12800
#define WT_O5 33280
#define WT_O6 82432

// ---------------------------------------------------------------------------
// packed f32x2 helpers
// ---------------------------------------------------------------------------
__device__ __forceinline__ u64 fma_x2(u64 a, u64 b, u64 c) {
    u64 d;
    asm("fma.rn.f32x2 %0, %1, %2, %3;" : "=l"(d) : "l"(a), "l"(b), "l"(c));
    return d;
}
__device__ __forceinline__ u64 pack2(float lo, float hi) {
    u64 d;
    asm("mov.b64 %0, {%1, %2};" : "=l"(d) : "f"(lo), "f"(hi));
    return d;
}
__device__ __forceinline__ float2 unpack2(u64 v) {
    float lo, hi;
    asm("mov.b64 {%0, %1}, %2;" : "=f"(lo), "=f"(hi) : "l"(v));
    return make_float2(lo, hi);
}

// ---------------------------------------------------------------------------
// Merged weight transpose
// ---------------------------------------------------------------------------
__global__ __launch_bounds__(256)
void transpose_all(const float* __restrict__ w0, const float* __restrict__ w1,
                   const float* __restrict__ w2, const float* __restrict__ w3,
                   const float* __restrict__ w4, const float* __restrict__ w5,
                   const float* __restrict__ w6, float* __restrict__ out) {
    int idx = blockIdx.x * blockDim.x + threadIdx.x;
    if (idx >= 197120) return;
    const float* src;
    int base, nf, cw, local;
    if      (idx < 1536)  { if (idx < 512) { src = w0; base = WT_O0; nf = 32;  cw = 16; local = idx; }
                            else           { src = w1; base = WT_O1; nf = 32;  cw = 32; local = idx - 512; } }
    else if (idx < 4608)  { src = w2; base = WT_O2; nf = 64;   cw = 48;  local = idx - 1536; }
    else if (idx < 12800) { src = w3; base = WT_O3; nf = 128;  cw = 64;  local = idx - 4608; }
    else if (idx < 33280) { src = w4; base = WT_O4; nf = 256;  cw = 80;  local = idx - 12800; }
    else if (idx < 82432) { src = w5; base = WT_O5; nf = 512;  cw = 96;  local = idx - 33280; }
    else                  { src = w6; base = WT_O6; nf = 1024; cw = 112; local = idx - 82432; }
    int f = local / cw;
    int r = local - f * cw;
    out[base + r * nf + f] = src[local];
}

// ---------------------------------------------------------------------------
// Conv stage — packed two-chunk accumulation via fma.rn.f32x2 (round 5 exact)
// ---------------------------------------------------------------------------
#define XS2_O1 0
#define XS2_O2 400
#define XS2_O3 816
#define XS2_O4 1232
#define XS2_O5 1664
#define XS2_O6 2096
#define XS2_O7 2544
#define XS2_TOT 2992

template <int W>
__device__ __forceinline__ float conv_max2(const u64* __restrict__ xs2,
                                           const float* __restrict__ wt,
                                           int nf, int f, float bias) {
    constexpr int NT = 51 - W;
    constexpr int TC = (NT + 1) / 2;
    constexpr int J  = TC + W - 1;
    u64 acc[TC];
#pragma unroll
    for (int t = 0; t < TC; t++) acc[t] = 0ULL;

#pragma unroll 2
    for (int c = 0; c < CDIM; c++) {
        u64 w2[W];
#pragma unroll
        for (int k = 0; k < W; k++) {
            float w = wt[(c * W + k) * nf + f];
            w2[k] = pack2(w, w);
        }
#pragma unroll
        for (int j = 0; j < J; j++) {
            u64 xv = xs2[c * J + j];
#pragma unroll
            for (int k = 0; k < W; k++) {
                int t = j - k;
                if (t >= 0 && t < TC) acc[t] = fma_x2(xv, w2[k], acc[t]);
            }
        }
    }
    float best = -3.4e38f;
#pragma unroll
    for (int t = 0; t < TC; t++) {
        float2 v = unpack2(acc[t]);
        best = fmaxf(best, fmaxf(v.x, v.y));
    }
    return fmaxf(best + bias, 0.0f);
}

__device__ __forceinline__ void store_split(float r, float* h,
                                            __nv_bfloat16* hi,
                                            __nv_bfloat16* lo, size_t o) {
    h[o] = r;
    __nv_bfloat16 hh = __float2bfloat16(r);
    hi[o] = hh;
    lo[o] = __float2bfloat16(r - __bfloat162float(hh));
}

__global__ __launch_bounds__(256)
void conv_kernel(const int*   __restrict__ chars,
                 const float* __restrict__ emb,
                 const float* __restrict__ wt,
                 const float* __restrict__ b0, const float* __restrict__ b1,
                 const float* __restrict__ b2, const float* __restrict__ b3,
                 const float* __restrict__ b4, const float* __restrict__ b5,
                 const float* __restrict__ b6,
                 float* __restrict__ h,
                 __nv_bfloat16* __restrict__ hhi,
                 __nv_bfloat16* __restrict__ hlo) {
    __shared__ float xs[CDIM * 51];
    __shared__ int   chs[MAXC];
    __shared__ u64   xs2[XS2_TOT];

    const int n   = blockIdx.x;
    const int tid = threadIdx.x;

    if (tid < MAXC) chs[tid] = chars[n * MAXC + tid];
    __syncthreads();
    for (int idx = tid; idx < MAXC * CDIM; idx += 256) {
        int t = idx >> 4;
        int c = idx & 15;
        xs[c * 51 + t] = emb[chs[t] * CDIM + c];
    }
    __syncthreads();

    {
        const int offs[7] = {XS2_O1, XS2_O2, XS2_O3, XS2_O4, XS2_O5, XS2_O6, XS2_O7};
        const int Js[7]   = {25, 26, 26, 27, 27, 28, 28};
        const int OFFs[7] = {25, 24, 24, 23, 23, 22, 22};
#pragma unroll
        for (int w = 0; w < 7; w++) {
            const int J = Js[w], OFF = OFFs[w];
            u64* dst = xs2 + offs[w];
            for (int idx = tid; idx < CDIM * J; idx += 256) {
                int c = idx / J;
                int j = idx - c * J;
                dst[idx] = pack2(xs[c * 51 + j], xs[c * 51 + OFF + j]);
            }
        }
    }
    __syncthreads();

    const size_t rowo = (size_t)n * NFILT;
    {
        int f = tid;
        float r;
        if (f < 32)        r = conv_max2<1>(xs2 + XS2_O1, wt + WT_O0, 32,  f,       b0[f]);
        else if (f < 64)   r = conv_max2<2>(xs2 + XS2_O2, wt + WT_O1, 32,  f - 32,  b1[f - 32]);
        else if (f < 128)  r = conv_max2<3>(xs2 + XS2_O3, wt + WT_O2, 64,  f - 64,  b2[f - 64]);
        else               r = conv_max2<4>(xs2 + XS2_O4, wt + WT_O3, 128, f - 128, b3[f - 128]);
        store_split(r, h, hhi, hlo, rowo + f);
    }
    {
        int f = tid;
        float r = conv_max2<5>(xs2 + XS2_O5, wt + WT_O4, 256, f, b4[f]);
        store_split(r, h, hhi, hlo, rowo + 256 + f);
    }
#pragma unroll
    for (int i = 0; i < 2; i++) {
        int f = tid + i * 256;
        float r = conv_max2<6>(xs2 + XS2_O6, wt + WT_O5, 512, f, b5[f]);
        store_split(r, h, hhi, hlo, rowo + 512 + f);
    }
#pragma unroll
    for (int i = 0; i < 4; i++) {
        int f = tid + i * 256;
        float r = conv_max2<7>(xs2 + XS2_O7, wt + WT_O6, 1024, f, b6[f]);
        store_split(r, h, hhi, hlo, rowo + 1024 + f);
    }
}

// ---------------------------------------------------------------------------
// fp32 -> (bf16 hi, bf16 lo) split (weights)
// ---------------------------------------------------------------------------
__global__ __launch_bounds__(256)
void cvt_split(const float* __restrict__ x,
               __nv_bfloat16* __restrict__ hi,
               __nv_bfloat16* __restrict__ lo, int n4) {
    int i = blockIdx.x * blockDim.x + threadIdx.x;
    if (i >= n4) return;
    float4 v = ((const float4*)x)[i];
    __nv_bfloat16 h0 = __float2bfloat16(v.x);
    __nv_bfloat16 h1 = __float2bfloat16(v.y);
    __nv_bfloat16 h2 = __float2bfloat16(v.z);
    __nv_bfloat16 h3 = __float2bfloat16(v.w);
    __nv_bfloat162* hp = (__nv_bfloat162*)hi + i * 2;
    __nv_bfloat162* lp = (__nv_bfloat162*)lo + i * 2;
    hp[0] = __halves2bfloat162(h0, h1);
    hp[1] = __halves2bfloat162(h2, h3);
    lp[0] = __halves2bfloat162(__float2bfloat16(v.x - __bfloat162float(h0)),
                               __float2bfloat16(v.y - __bfloat162float(h1)));
    lp[1] = __halves2bfloat162(__float2bfloat16(v.z - __bfloat162float(h2)),
                               __float2bfloat16(v.w - __bfloat162float(h3)));
}

// ---------------------------------------------------------------------------
// mma helpers
// ---------------------------------------------------------------------------
__device__ __forceinline__ void ldm_x4(uint32_t addr, uint32_t& r0, uint32_t& r1,
                                       uint32_t& r2, uint32_t& r3) {
    asm volatile("ldmatrix.sync.aligned.m8n8.x4.shared.b16 {%0,%1,%2,%3}, [%4];"
                 : "=r"(r0), "=r"(r1), "=r"(r2), "=r"(r3) : "r"(addr));
}
__device__ __forceinline__ void mma16816(float* c, const uint32_t* a,
                                         uint32_t b0, uint32_t b1) {
    asm volatile(
        "mma.sync.aligned.m16n8k16.row.col.f32.bf16.bf16.f32 "
        "{%0,%1,%2,%3}, {%4,%5,%6,%7}, {%8,%9}, {%0,%1,%2,%3};"
        : "+f"(c[0]), "+f"(c[1]), "+f"(c[2]), "+f"(c[3])
        : "r"(a[0]), "r"(a[1]), "r"(a[2]), "r"(a[3]), "r"(b0), "r"(b1));
}
__device__ __forceinline__ void cp16(uint32_t s, const void* g) {
    asm volatile("cp.async.cg.shared.global [%0], [%1], 16;" :: "r"(s), "l"(g));
}
#define CP_COMMIT() asm volatile("cp.async.commit_group;" ::: "memory")
#define CP_WAIT(n)  asm volatile("cp.async.wait_group %0;" :: "n"(n) : "memory")

__device__ __forceinline__ uint32_t smem_u32(const void* p) {
    uint32_t a;
    asm("{ .reg .u64 t; cvta.to.shared.u64 t, %1; cvt.u32.u64 %0, t; }"
        : "=r"(a) : "l"(p));
    return a;
}

// ---------------------------------------------------------------------------
// bf16x3 GEMM, CTA 128x256, 512 threads, 16 warps of 32x64 tiles,
// BK=64, 3 stages (96 iters). Fragment mapping = verified gemm_prj.
// ---------------------------------------------------------------------------
#define HWSTR   72                               // BK=64 stride (bf16)
#define BIG_ITERS 96                             // 6144 / 64
#define BIG_ASTG (128 * HWSTR * 2)               // 18432
#define BIG_BSTG (256 * HWSTR * 2)               // 36864
#define BIG_DSMEM (3 * (BIG_ASTG + BIG_BSTG))    // 165888

__global__ __launch_bounds__(512)
void gemm_big(const __nv_bfloat16* __restrict__ Ahi,
              const __nv_bfloat16* __restrict__ Alo,
              const __nv_bfloat16* __restrict__ Bhi,
              const __nv_bfloat16* __restrict__ Blo,
              const float* __restrict__ bias,
              float* __restrict__ C, int Ntot) {
    extern __shared__ __nv_bfloat16 sm[];
    const uint32_t sbase = smem_u32(sm);

    const int tid  = threadIdx.x;
    const int lane = tid & 31;
    const int warp = tid >> 5;          // 0..15
    const int wm   = warp & 3;          // 4 m-warps of 32 rows
    const int wn   = warp >> 2;         // 4 n-warps of 64 cols
    const int bm   = blockIdx.y * 128;
    const int bn   = blockIdx.x * 256;

    const int q2 = lane >> 3;
    const int lr = lane & 7;
    const int aMrow = wm * 32 + (q2 & 1) * 8 + lr;
    const int aKoff = (q2 >> 1) * 8;
    const int bNrow = wn * 64 + (q2 >> 1) * 8 + lr;
    const int bKoff = (q2 & 1) * 8;

    float acc[2][8][4];
#pragma unroll
    for (int i = 0; i < 2; i++)
#pragma unroll
        for (int j = 0; j < 8; j++)
#pragma unroll
            for (int r = 0; r < 4; r++) acc[i][j][r] = 0.0f;

    // per-stage loads: A 1024 chunks of 16B (2/thread), B 2048 (4/thread)
    auto issue = [&](int it, int s) {
        const int seg  = it >> 5;
        const int kloc = (it & 31) * 64;
        const __nv_bfloat16* Asrc = (seg < 2) ? Ahi : Alo;
        const __nv_bfloat16* Bsrc = (seg == 1) ? Blo : Bhi;
        const uint32_t ab = sbase + (uint32_t)s * BIG_ASTG;
        const uint32_t bb = sbase + 3 * BIG_ASTG + (uint32_t)s * BIG_BSTG;
#pragma unroll
        for (int j = 0; j < 2; j++) {
            const int idx = tid * 2 + j;
            const int r = idx >> 3, c = idx & 7;
            cp16(ab + (uint32_t)(r * HWSTR + c * 8) * 2,
                 Asrc + (size_t)(bm + r) * KDIM + kloc + c * 8);
        }
#pragma unroll
        for (int j = 0; j < 4; j++) {
            const int idx = tid * 4 + j;
            const int r = idx >> 3, c = idx & 7;
            cp16(bb + (uint32_t)(r * HWSTR + c * 8) * 2,
                 Bsrc + (size_t)(bn + r) * KDIM + kloc + c * 8);
        }
    };

    issue(0, 0); CP_COMMIT();
    issue(1, 1); CP_COMMIT();

    for (int it = 0; it < BIG_ITERS; it++) {
        CP_WAIT(1);
        __syncthreads();
        if (it + 2 < BIG_ITERS) issue(it + 2, (it + 2) % 3);
        CP_COMMIT();

        const int s = it % 3;
        const uint32_t sAb = sbase + (uint32_t)s * BIG_ASTG;
        const uint32_t sBb = sbase + 3 * BIG_ASTG + (uint32_t)s * BIG_BSTG;
#pragma unroll
        for (int q = 0; q < 4; q++) {
            uint32_t a[2][4];
#pragma unroll
            for (int mf = 0; mf < 2; mf++)
                ldm_x4(sAb + (uint32_t)(((aMrow + mf * 16) * HWSTR + q * 16 + aKoff) * 2),
                       a[mf][0], a[mf][1], a[mf][2], a[mf][3]);
            uint32_t b[4][4];
#pragma unroll
            for (int p = 0; p < 4; p++)
                ldm_x4(sBb + (uint32_t)(((bNrow + p * 16) * HWSTR + q * 16 + bKoff) * 2),
                       b[p][0], b[p][1], b[p][2], b[p][3]);
#pragma unroll
            for (int mf = 0; mf < 2; mf++)
#pragma unroll
                for (int nf = 0; nf < 8; nf++)
                    mma16816(acc[mf][nf], a[mf],
                             b[nf >> 1][(nf & 1) * 2 + 0],
                             b[nf >> 1][(nf & 1) * 2 + 1]);
        }
    }

    const int mbase = bm + wm * 32 + (lane >> 2);
    const int nbase = bn + wn * 64 + (lane & 3) * 2;
#pragma unroll
    for (int mf = 0; mf < 2; mf++) {
#pragma unroll
        for (int nf = 0; nf < 8; nf++) {
            const int c = nbase + nf * 8;
            const float bi0 = __ldg(bias + c);
            const float bi1 = __ldg(bias + c + 1);
            const int r0 = mbase + mf * 16;
            *(float2*)(C + (size_t)r0 * Ntot + c) =
                make_float2(acc[mf][nf][0] + bi0, acc[mf][nf][1] + bi1);
            *(float2*)(C + (size_t)(r0 + 8) * Ntot + c) =
                make_float2(acc[mf][nf][2] + bi0, acc[mf][nf][3] + bi1);
        }
    }
}

// ---------------------------------------------------------------------------
// Projection GEMM: CTA 128x128, warp 32x64, BK=32, 4 stages (round 5 exact)
// ---------------------------------------------------------------------------
#define GSTR   40
#define NSTAGE 4
#define GITERS 192
#define PR_STG (128 * GSTR * 2)               // 10240
#define PR_DSMEM (NSTAGE * 2 * PR_STG)        // 81920

__global__ __launch_bounds__(256, 2)
void gemm_prj(const __nv_bfloat16* __restrict__ Ahi,
              const __nv_bfloat16* __restrict__ Alo,
              const __nv_bfloat16* __restrict__ Bhi,
              const __nv_bfloat16* __restrict__ Blo,
              const float* __restrict__ bias,
              float* __restrict__ C, int Ntot) {
    extern __shared__ __nv_bfloat16 sm[];
    const uint32_t sbase = smem_u32(sm);

    const int tid  = threadIdx.x;
    const int lane = tid & 31;
    const int warp = tid >> 5;
    const int wm   = warp & 3;
    const int wn   = warp >> 2;
    const int bm   = blockIdx.y * 128;
    const int bn   = blockIdx.x * 128;

    const int lrow = tid >> 1;
    const int lc0  = (tid & 1) * 2;

    const int q2 = lane >> 3;
    const int lr = lane & 7;
    const int aMrow = wm * 32 + (q2 & 1) * 8 + lr;
    const int aKoff = (q2 >> 1) * 8;
    const int bNrow = wn * 64 + (q2 >> 1) * 8 + lr;
    const int bKoff = (q2 & 1) * 8;

    float acc[2][8][4];
#pragma unroll
    for (int i = 0; i < 2; i++)
#pragma unroll
        for (int j = 0; j < 8; j++)
#pragma unroll
            for (int r = 0; r < 4; r++) acc[i][j][r] = 0.0f;

    auto issue = [&](int it, int s) {
        const int seg  = it >> 6;
        const int kloc = (it & 63) * 32;
        const __nv_bfloat16* Asrc = (seg < 2) ? Ahi : Alo;
        const __nv_bfloat16* Bsrc = (seg == 1) ? Blo : Bhi;
        const uint32_t ab = sbase + (uint32_t)s * (2 * PR_STG);
        const uint32_t bb = ab + PR_STG;
#pragma unroll
        for (int j = 0; j < 2; j++) {
            const int c = lc0 + j;
            cp16(ab + (uint32_t)(lrow * GSTR + c * 8) * 2,
                 Asrc + (size_t)(bm + lrow) * KDIM + kloc + c * 8);
            cp16(bb + (uint32_t)(lrow * GSTR + c * 8) * 2,
                 Bsrc + (size_t)(bn + lrow) * KDIM + kloc + c * 8);
        }
    };

#pragma unroll
    for (int s = 0; s < NSTAGE - 1; s++) {
        issue(s, s);
        CP_COMMIT();
    }

    for (int it = 0; it < GITERS; it++) {
        CP_WAIT(NSTAGE - 2);
        __syncthreads();
        if (it + NSTAGE - 1 < GITERS) issue(it + NSTAGE - 1, (it + NSTAGE - 1) % NSTAGE);
        CP_COMMIT();

        const int s = it % NSTAGE;
        const uint32_t sAb = sbase + (uint32_t)s * (2 * PR_STG);
        const uint32_t sBb = sAb + PR_STG;
#pragma unroll
        for (int q = 0; q < 2; q++) {
            uint32_t a[2][4];
#pragma unroll
            for (int mf = 0; mf < 2; mf++)
                ldm_x4(sAb + (uint32_t)(((aMrow + mf * 16) * GSTR + q * 16 + aKoff) * 2),
                       a[mf][0], a[mf][1], a[mf][2], a[mf][3]);
            uint32_t b[4][4];
#pragma unroll
            for (int p = 0; p < 4; p++)
                ldm_x4(sBb + (uint32_t)(((bNrow + p * 16) * GSTR + q * 16 + bKoff) * 2),
                       b[p][0], b[p][1], b[p][2], b[p][3]);
#pragma unroll
            for (int mf = 0; mf < 2; mf++)
#pragma unroll
                for (int nf = 0; nf < 8; nf++)
                    mma16816(acc[mf][nf], a[mf],
                             b[nf >> 1][(nf & 1) * 2 + 0],
                             b[nf >> 1][(nf & 1) * 2 + 1]);
        }
    }

    const int mbase = bm + wm * 32 + (lane >> 2);
    const int nbase = bn + wn * 64 + (lane & 3) * 2;
#pragma unroll
    for (int mf = 0; mf < 2; mf++) {
#pragma unroll
        for (int nf = 0; nf < 8; nf++) {
            const int c = nbase + nf * 8;
            const float bi0 = __ldg(bias + c);
            const float bi1 = __ldg(bias + c + 1);
            const int r0 = mbase + mf * 16;
            *(float2*)(C + (size_t)r0 * Ntot + c) =
                make_float2(acc[mf][nf][0] + bi0, acc[mf][nf][1] + bi1);
            *(float2*)(C + (size_t)(r0 + 8) * Ntot + c) =
                make_float2(acc[mf][nf][2] + bi0, acc[mf][nf][3] + bi1);
        }
    }
}

// ---------------------------------------------------------------------------
// Highway combine + fused bf16 hi/lo split of new h
// ---------------------------------------------------------------------------
__global__ __launch_bounds__(256)
void highway_kernel(const float* __restrict__ p, float* __restrict__ h,
                    __nv_bfloat16* __restrict__ hhi,
                    __nv_bfloat16* __restrict__ hlo) {
    int idx = blockIdx.x * blockDim.x + threadIdx.x;
    int total = NTOK * (NFILT / 4);
    if (idx >= total) return;
    int m  = idx / (NFILT / 4);
    int j4 = idx % (NFILT / 4);

    const float4 pt = *(const float4*)(p + (size_t)m * (2 * NFILT) + j4 * 4);
    const float4 pg = *(const float4*)(p + (size_t)m * (2 * NFILT) + NFILT + j4 * 4);
    float4 hv = *(float4*)(h + (size_t)m * NFILT + j4 * 4);

    float g;
    g = 1.0f / (1.0f + expf(-pg.x)); hv.x = g * hv.x + (1.0f - g) * fmaxf(pt.x, 0.0f);
    g = 1.0f / (1.0f + expf(-pg.y)); hv.y = g * hv.y + (1.0f - g) * fmaxf(pt.y, 0.0f);
    g = 1.0f / (1.0f + expf(-pg.z)); hv.z = g * hv.z + (1.0f - g) * fmaxf(pt.z, 0.0f);
    g = 1.0f / (1.0f + expf(-pg.w)); hv.w = g * hv.w + (1.0f - g) * fmaxf(pt.w, 0.0f);

    *(float4*)(h + (size_t)m * NFILT + j4 * 4) = hv;

    __nv_bfloat16 h0 = __float2bfloat16(hv.x);
    __nv_bfloat16 h1 = __float2bfloat16(hv.y);
    __nv_bfloat16 h2 = __float2bfloat16(hv.z);
    __nv_bfloat16 h3 = __float2bfloat16(hv.w);
    __nv_bfloat162* hp = (__nv_bfloat162*)(hhi + (size_t)m * NFILT + j4 * 4);
    __nv_bfloat162* lp = (__nv_bfloat162*)(hlo + (size_t)m * NFILT + j4 * 4);
    hp[0] = __halves2bfloat162(h0, h1);
    hp[1] = __halves2bfloat162(h2, h3);
    lp[0] = __halves2bfloat162(__float2bfloat16(hv.x - __bfloat162float(h0)),
                               __float2bfloat16(hv.y - __bfloat162float(h1)));
    lp[1] = __halves2bfloat162(__float2bfloat16(hv.z - __bfloat162float(h2)),
                               __float2bfloat16(hv.w - __bfloat162float(h3)));
}

// ---------------------------------------------------------------------------
// Launch — my-index-3 (= ncu's profiled slot) stays gemm_big
// ---------------------------------------------------------------------------
extern "C" void kernel_launch(void* const* d_in, const int* in_sizes, int n_in,
                              void* d_out, int out_size) {
    const int*   chars  = (const int*)d_in[1];
    const float* emb    = (const float*)d_in[2];
    const float* cw[7], *cb[7];
    for (int i = 0; i < 7; i++) {
        cw[i] = (const float*)d_in[3 + 2 * i];
        cb[i] = (const float*)d_in[4 + 2 * i];
    }
    const float* hw_w0  = (const float*)d_in[17];
    const float* hw_b0  = (const float*)d_in[18];
    const float* hw_w1  = (const float*)d_in[19];
    const float* hw_b1  = (const float*)d_in[20];
    const float* proj_w = (const float*)d_in[21];
    const float* proj_b = (const float*)d_in[22];
    float* out = (float*)d_out;

    static float *hbuf = nullptr, *pbuf = nullptr, *wtbuf = nullptr;
    static __nv_bfloat16 *hhi, *hlo, *w0hi, *w0lo, *w1hi, *w1lo, *wphi, *wplo;
    if (!hbuf) {
        cudaGetSymbolAddress((void**)&hbuf,  g_h);
        cudaGetSymbolAddress((void**)&pbuf,  g_p);
        cudaGetSymbolAddress((void**)&wtbuf, g_wt);
        cudaGetSymbolAddress((void**)&hhi,   g_hhi);
        cudaGetSymbolAddress((void**)&hlo,   g_hlo);
        cudaGetSymbolAddress((void**)&w0hi,  g_w0hi);
        cudaGetSymbolAddress((void**)&w0lo,  g_w0lo);
        cudaGetSymbolAddress((void**)&w1hi,  g_w1hi);
        cudaGetSymbolAddress((void**)&w1lo,  g_w1lo);
        cudaGetSymbolAddress((void**)&wphi,  g_wphi);
        cudaGetSymbolAddress((void**)&wplo,  g_wplo);
        cudaFuncSetAttribute(gemm_big,
                             cudaFuncAttributeMaxDynamicSharedMemorySize,
                             BIG_DSMEM);
        cudaFuncSetAttribute(gemm_prj,
                             cudaFuncAttributeMaxDynamicSharedMemorySize,
                             PR_DSMEM);
    }

    dim3 blk(256);
    const int nW  = 2 * NFILT * NFILT;
    const int nWP = PROJ * NFILT;
    auto cvb = [](int n) { return (n / 4 + 255) / 256; };

    dim3 grid_hw(2 * NFILT / 256, NTOK / 128);   // (16, 32)
    dim3 grid_pr(PROJ / 128, NTOK / 128);        // (4, 32)
    int hw_blocks = (NTOK * (NFILT / 4) + 255) / 256;

    // index 0: merged conv-weight transpose
    transpose_all<<<(197120 + 255) / 256, blk>>>(cw[0], cw[1], cw[2], cw[3],
                                                 cw[4], cw[5], cw[6], wtbuf);
    // index 1: w0 split
    cvt_split<<<cvb(nW), blk>>>(hw_w0, w0hi, w0lo, nW / 4);
    // index 2: conv
    conv_kernel<<<NTOK, 256>>>(chars, emb, wtbuf,
                               cb[0], cb[1], cb[2], cb[3], cb[4], cb[5], cb[6],
                               hbuf, hhi, hlo);
    // index 3: highway-0 GEMM (ncu slot) — 512 threads, BK=64
    gemm_big<<<grid_hw, dim3(512), BIG_DSMEM>>>(hhi, hlo, w0hi, w0lo, hw_b0,
                                                pbuf, 2 * NFILT);
    // index 4: highway-0 combine
    highway_kernel<<<hw_blocks, blk>>>(pbuf, hbuf, hhi, hlo);
    // index 5: w1 split
    cvt_split<<<cvb(nW), blk>>>(hw_w1, w1hi, w1lo, nW / 4);
    // index 6: highway-1 GEMM
    gemm_big<<<grid_hw, dim3(512), BIG_DSMEM>>>(hhi, hlo, w1hi, w1lo, hw_b1,
                                                pbuf, 2 * NFILT);
    // index 7: highway-1 combine
    highway_kernel<<<hw_blocks, blk>>>(pbuf, hbuf, hhi, hlo);
    // index 8: proj weight split
    cvt_split<<<cvb(nWP), blk>>>(proj_w, wphi, wplo, nWP / 4);
    // index 9: projection
    gemm_prj<<<grid_pr, blk, PR_DSMEM>>>(hhi, hlo, wphi, wplo, proj_b,
                                         out, PROJ);
}

// round 13
// speedup vs baseline: 1.1182x; 1.1182x over previous
#include <cuda_runtime.h>
#include <cuda_bf16.h>
#include <math.h>
#include <stdint.h>

// ---------------------------------------------------------------------------
// ConvTokenEmbedder: char CNN + highway x2 + projection
// Round 13: ALL GEMMs use the verified 128x128 / 256-thread / BK=32 / 4-stage
//           kernel with 2 CTAs per SM (two independent barrier domains).
//           Rest = round-11 (3006us) verbatim.
// ---------------------------------------------------------------------------

#define NTOK   4096
#define NFILT  2048
#define PROJ   512
#define MAXC   50
#define CDIM   16
#define KDIM   2048

typedef unsigned long long u64;

// Scratch
__device__ float g_h[NTOK * NFILT];
__device__ float g_p[NTOK * 2 * NFILT];
__device__ float g_wt[197120];
__device__ __nv_bfloat16 g_hhi[NTOK * NFILT];
__device__ __nv_bfloat16 g_hlo[NTOK * NFILT];
__device__ __nv_bfloat16 g_w0hi[2 * NFILT * NFILT];
__device__ __nv_bfloat16 g_w0lo[2 * NFILT * NFILT];
__device__ __nv_bfloat16 g_w1hi[2 * NFILT * NFILT];
__device__ __nv_bfloat16 g_w1lo[2 * NFILT * NFILT];
__device__ __nv_bfloat16 g_wphi[PROJ * NFILT];
__device__ __nv_bfloat16 g_wplo[PROJ * NFILT];

#define WT_O0 0
#define WT_O1 512
#define WT_O2 1536
#define WT_O3 4608
#define WT_O4 12800
#define WT_O5 33280
#define WT_O6 82432

// ---------------------------------------------------------------------------
// packed f32x2 helpers
// ---------------------------------------------------------------------------
__device__ __forceinline__ u64 fma_x2(u64 a, u64 b, u64 c) {
    u64 d;
    asm("fma.rn.f32x2 %0, %1, %2, %3;" : "=l"(d) : "l"(a), "l"(b), "l"(c));
    return d;
}
__device__ __forceinline__ u64 pack2(float lo, float hi) {
    u64 d;
    asm("mov.b64 %0, {%1, %2};" : "=l"(d) : "f"(lo), "f"(hi));
    return d;
}
__device__ __forceinline__ float2 unpack2(u64 v) {
    float lo, hi;
    asm("mov.b64 {%0, %1}, %2;" : "=f"(lo), "=f"(hi) : "l"(v));
    return make_float2(lo, hi);
}

// ---------------------------------------------------------------------------
// Merged weight transpose
// ---------------------------------------------------------------------------
__global__ __launch_bounds__(256)
void transpose_all(const float* __restrict__ w0, const float* __restrict__ w1,
                   const float* __restrict__ w2, const float* __restrict__ w3,
                   const float* __restrict__ w4, const float* __restrict__ w5,
                   const float* __restrict__ w6, float* __restrict__ out) {
    int idx = blockIdx.x * blockDim.x + threadIdx.x;
    if (idx >= 197120) return;
    const float* src;
    int base, nf, cw, local;
    if      (idx < 1536)  { if (idx < 512) { src = w0; base = WT_O0; nf = 32;  cw = 16; local = idx; }
                            else           { src = w1; base = WT_O1; nf = 32;  cw = 32; local = idx - 512; } }
    else if (idx < 4608)  { src = w2; base = WT_O2; nf = 64;   cw = 48;  local = idx - 1536; }
    else if (idx < 12800) { src = w3; base = WT_O3; nf = 128;  cw = 64;  local = idx - 4608; }
    else if (idx < 33280) { src = w4; base = WT_O4; nf = 256;  cw = 80;  local = idx - 12800; }
    else if (idx < 82432) { src = w5; base = WT_O5; nf = 512;  cw = 96;  local = idx - 33280; }
    else                  { src = w6; base = WT_O6; nf = 1024; cw = 112; local = idx - 82432; }
    int f = local / cw;
    int r = local - f * cw;
    out[base + r * nf + f] = src[local];
}

// ---------------------------------------------------------------------------
// Conv stage — packed two-chunk accumulation via fma.rn.f32x2 (round 5 exact)
// ---------------------------------------------------------------------------
#define XS2_O1 0
#define XS2_O2 400
#define XS2_O3 816
#define XS2_O4 1232
#define XS2_O5 1664
#define XS2_O6 2096
#define XS2_O7 2544
#define XS2_TOT 2992

template <int W>
__device__ __forceinline__ float conv_max2(const u64* __restrict__ xs2,
                                           const float* __restrict__ wt,
                                           int nf, int f, float bias) {
    constexpr int NT = 51 - W;
    constexpr int TC = (NT + 1) / 2;
    constexpr int J  = TC + W - 1;
    u64 acc[TC];
#pragma unroll
    for (int t = 0; t < TC; t++) acc[t] = 0ULL;

#pragma unroll 2
    for (int c = 0; c < CDIM; c++) {
        u64 w2[W];
#pragma unroll
        for (int k = 0; k < W; k++) {
            float w = wt[(c * W + k) * nf + f];
            w2[k] = pack2(w, w);
        }
#pragma unroll
        for (int j = 0; j < J; j++) {
            u64 xv = xs2[c * J + j];
#pragma unroll
            for (int k = 0; k < W; k++) {
                int t = j - k;
                if (t >= 0 && t < TC) acc[t] = fma_x2(xv, w2[k], acc[t]);
            }
        }
    }
    float best = -3.4e38f;
#pragma unroll
    for (int t = 0; t < TC; t++) {
        float2 v = unpack2(acc[t]);
        best = fmaxf(best, fmaxf(v.x, v.y));
    }
    return fmaxf(best + bias, 0.0f);
}

__device__ __forceinline__ void store_split(float r, float* h,
                                            __nv_bfloat16* hi,
                                            __nv_bfloat16* lo, size_t o) {
    h[o] = r;
    __nv_bfloat16 hh = __float2bfloat16(r);
    hi[o] = hh;
    lo[o] = __float2bfloat16(r - __bfloat162float(hh));
}

__global__ __launch_bounds__(256)
void conv_kernel(const int*   __restrict__ chars,
                 const float* __restrict__ emb,
                 const float* __restrict__ wt,
                 const float* __restrict__ b0, const float* __restrict__ b1,
                 const float* __restrict__ b2, const float* __restrict__ b3,
                 const float* __restrict__ b4, const float* __restrict__ b5,
                 const float* __restrict__ b6,
                 float* __restrict__ h,
                 __nv_bfloat16* __restrict__ hhi,
                 __nv_bfloat16* __restrict__ hlo) {
    __shared__ float xs[CDIM * 51];
    __shared__ int   chs[MAXC];
    __shared__ u64   xs2[XS2_TOT];

    const int n   = blockIdx.x;
    const int tid = threadIdx.x;

    if (tid < MAXC) chs[tid] = chars[n * MAXC + tid];
    __syncthreads();
    for (int idx = tid; idx < MAXC * CDIM; idx += 256) {
        int t = idx >> 4;
        int c = idx & 15;
        xs[c * 51 + t] = emb[chs[t] * CDIM + c];
    }
    __syncthreads();

    {
        const int offs[7] = {XS2_O1, XS2_O2, XS2_O3, XS2_O4, XS2_O5, XS2_O6, XS2_O7};
        const int Js[7]   = {25, 26, 26, 27, 27, 28, 28};
        const int OFFs[7] = {25, 24, 24, 23, 23, 22, 22};
#pragma unroll
        for (int w = 0; w < 7; w++) {
            const int J = Js[w], OFF = OFFs[w];
            u64* dst = xs2 + offs[w];
            for (int idx = tid; idx < CDIM * J; idx += 256) {
                int c = idx / J;
                int j = idx - c * J;
                dst[idx] = pack2(xs[c * 51 + j], xs[c * 51 + OFF + j]);
            }
        }
    }
    __syncthreads();

    const size_t rowo = (size_t)n * NFILT;
    {
        int f = tid;
        float r;
        if (f < 32)        r = conv_max2<1>(xs2 + XS2_O1, wt + WT_O0, 32,  f,       b0[f]);
        else if (f < 64)   r = conv_max2<2>(xs2 + XS2_O2, wt + WT_O1, 32,  f - 32,  b1[f - 32]);
        else if (f < 128)  r = conv_max2<3>(xs2 + XS2_O3, wt + WT_O2, 64,  f - 64,  b2[f - 64]);
        else               r = conv_max2<4>(xs2 + XS2_O4, wt + WT_O3, 128, f - 128, b3[f - 128]);
        store_split(r, h, hhi, hlo, rowo + f);
    }
    {
        int f = tid;
        float r = conv_max2<5>(xs2 + XS2_O5, wt + WT_O4, 256, f, b4[f]);
        store_split(r, h, hhi, hlo, rowo + 256 + f);
    }
#pragma unroll
    for (int i = 0; i < 2; i++) {
        int f = tid + i * 256;
        float r = conv_max2<6>(xs2 + XS2_O6, wt + WT_O5, 512, f, b5[f]);
        store_split(r, h, hhi, hlo, rowo + 512 + f);
    }
#pragma unroll
    for (int i = 0; i < 4; i++) {
        int f = tid + i * 256;
        float r = conv_max2<7>(xs2 + XS2_O7, wt + WT_O6, 1024, f, b6[f]);
        store_split(r, h, hhi, hlo, rowo + 1024 + f);
    }
}

// ---------------------------------------------------------------------------
// fp32 -> (bf16 hi, bf16 lo) split (weights)
// ---------------------------------------------------------------------------
__global__ __launch_bounds__(256)
void cvt_split(const float* __restrict__ x,
               __nv_bfloat16* __restrict__ hi,
               __nv_bfloat16* __restrict__ lo, int n4) {
    int i = blockIdx.x * blockDim.x + threadIdx.x;
    if (i >= n4) return;
    float4 v = ((const float4*)x)[i];
    __nv_bfloat16 h0 = __float2bfloat16(v.x);
    __nv_bfloat16 h1 = __float2bfloat16(v.y);
    __nv_bfloat16 h2 = __float2bfloat16(v.z);
    __nv_bfloat16 h3 = __float2bfloat16(v.w);
    __nv_bfloat162* hp = (__nv_bfloat162*)hi + i * 2;
    __nv_bfloat162* lp = (__nv_bfloat162*)lo + i * 2;
    hp[0] = __halves2bfloat162(h0, h1);
    hp[1] = __halves2bfloat162(h2, h3);
    lp[0] = __halves2bfloat162(__float2bfloat16(v.x - __bfloat162float(h0)),
                               __float2bfloat16(v.y - __bfloat162float(h1)));
    lp[1] = __halves2bfloat162(__float2bfloat16(v.z - __bfloat162float(h2)),
                               __float2bfloat16(v.w - __bfloat162float(h3)));
}

// ---------------------------------------------------------------------------
// mma helpers — BK=32 / 4-stage
// ---------------------------------------------------------------------------
#define GSTR   40
#define NSTAGE 4
#define GITERS 192                   // 6144 / 32

__device__ __forceinline__ void ldm_x4(uint32_t addr, uint32_t& r0, uint32_t& r1,
                                       uint32_t& r2, uint32_t& r3) {
    asm volatile("ldmatrix.sync.aligned.m8n8.x4.shared.b16 {%0,%1,%2,%3}, [%4];"
                 : "=r"(r0), "=r"(r1), "=r"(r2), "=r"(r3) : "r"(addr));
}
__device__ __forceinline__ void mma16816(float* c, const uint32_t* a,
                                         uint32_t b0, uint32_t b1) {
    asm volatile(
        "mma.sync.aligned.m16n8k16.row.col.f32.bf16.bf16.f32 "
        "{%0,%1,%2,%3}, {%4,%5,%6,%7}, {%8,%9}, {%0,%1,%2,%3};"
        : "+f"(c[0]), "+f"(c[1]), "+f"(c[2]), "+f"(c[3])
        : "r"(a[0]), "r"(a[1]), "r"(a[2]), "r"(a[3]), "r"(b0), "r"(b1));
}
__device__ __forceinline__ void cp16(uint32_t s, const void* g) {
    asm volatile("cp.async.cg.shared.global [%0], [%1], 16;" :: "r"(s), "l"(g));
}
#define CP_COMMIT() asm volatile("cp.async.commit_group;" ::: "memory")
#define CP_WAIT(n)  asm volatile("cp.async.wait_group %0;" :: "n"(n) : "memory")

__device__ __forceinline__ uint32_t smem_u32(const void* p) {
    uint32_t a;
    asm("{ .reg .u64 t; cvta.to.shared.u64 t, %1; cvt.u32.u64 %0, t; }"
        : "=r"(a) : "l"(p));
    return a;
}

// ---------------------------------------------------------------------------
// bf16x3 GEMM: CTA 128x128, 256 threads, warp 32x64, BK=32, 4 stages,
// 2 CTAs/SM (verified round-5 gemm_prj). Used for ALL GEMMs.
// ---------------------------------------------------------------------------
#define PR_STG (128 * GSTR * 2)               // 10240
#define PR_DSMEM (NSTAGE * 2 * PR_STG)        // 81920

__global__ __launch_bounds__(256, 2)
void gemm_prj(const __nv_bfloat16* __restrict__ Ahi,
              const __nv_bfloat16* __restrict__ Alo,
              const __nv_bfloat16* __restrict__ Bhi,
              const __nv_bfloat16* __restrict__ Blo,
              const float* __restrict__ bias,
              float* __restrict__ C, int Ntot) {
    extern __shared__ __nv_bfloat16 sm[];
    const uint32_t sbase = smem_u32(sm);

    const int tid  = threadIdx.x;
    const int lane = tid & 31;
    const int warp = tid >> 5;
    const int wm   = warp & 3;
    const int wn   = warp >> 2;
    const int bm   = blockIdx.y * 128;
    const int bn   = blockIdx.x * 128;

    const int lrow = tid >> 1;
    const int lc0  = (tid & 1) * 2;

    const int q2 = lane >> 3;
    const int lr = lane & 7;
    const int aMrow = wm * 32 + (q2 & 1) * 8 + lr;
    const int aKoff = (q2 >> 1) * 8;
    const int bNrow = wn * 64 + (q2 >> 1) * 8 + lr;
    const int bKoff = (q2 & 1) * 8;

    float acc[2][8][4];
#pragma unroll
    for (int i = 0; i < 2; i++)
#pragma unroll
        for (int j = 0; j < 8; j++)
#pragma unroll
            for (int r = 0; r < 4; r++) acc[i][j][r] = 0.0f;

    auto issue = [&](int it, int s) {
        const int seg  = it >> 6;
        const int kloc = (it & 63) * 32;
        const __nv_bfloat16* Asrc = (seg < 2) ? Ahi : Alo;
        const __nv_bfloat16* Bsrc = (seg == 1) ? Blo : Bhi;
        const uint32_t ab = sbase + (uint32_t)s * (2 * PR_STG);
        const uint32_t bb = ab + PR_STG;
#pragma unroll
        for (int j = 0; j < 2; j++) {
            const int c = lc0 + j;
            cp16(ab + (uint32_t)(lrow * GSTR + c * 8) * 2,
                 Asrc + (size_t)(bm + lrow) * KDIM + kloc + c * 8);
            cp16(bb + (uint32_t)(lrow * GSTR + c * 8) * 2,
                 Bsrc + (size_t)(bn + lrow) * KDIM + kloc + c * 8);
        }
    };

#pragma unroll
    for (int s = 0; s < NSTAGE - 1; s++) {
        issue(s, s);
        CP_COMMIT();
    }

    for (int it = 0; it < GITERS; it++) {
        CP_WAIT(NSTAGE - 2);
        __syncthreads();
        if (it + NSTAGE - 1 < GITERS) issue(it + NSTAGE - 1, (it + NSTAGE - 1) % NSTAGE);
        CP_COMMIT();

        const int s = it % NSTAGE;
        const uint32_t sAb = sbase + (uint32_t)s * (2 * PR_STG);
        const uint32_t sBb = sAb + PR_STG;
#pragma unroll
        for (int q = 0; q < 2; q++) {
            uint32_t a[2][4];
#pragma unroll
            for (int mf = 0; mf < 2; mf++)
                ldm_x4(sAb + (uint32_t)(((aMrow + mf * 16) * GSTR + q * 16 + aKoff) * 2),
                       a[mf][0], a[mf][1], a[mf][2], a[mf][3]);
            uint32_t b[4][4];
#pragma unroll
            for (int p = 0; p < 4; p++)
                ldm_x4(sBb + (uint32_t)(((bNrow + p * 16) * GSTR + q * 16 + bKoff) * 2),
                       b[p][0], b[p][1], b[p][2], b[p][3]);
#pragma unroll
            for (int mf = 0; mf < 2; mf++)
#pragma unroll
                for (int nf = 0; nf < 8; nf++)
                    mma16816(acc[mf][nf], a[mf],
                             b[nf >> 1][(nf & 1) * 2 + 0],
                             b[nf >> 1][(nf & 1) * 2 + 1]);
        }
    }

    const int mbase = bm + wm * 32 + (lane >> 2);
    const int nbase = bn + wn * 64 + (lane & 3) * 2;
#pragma unroll
    for (int mf = 0; mf < 2; mf++) {
#pragma unroll
        for (int nf = 0; nf < 8; nf++) {
            const int c = nbase + nf * 8;
            const float bi0 = __ldg(bias + c);
            const float bi1 = __ldg(bias + c + 1);
            const int r0 = mbase + mf * 16;
            *(float2*)(C + (size_t)r0 * Ntot + c) =
                make_float2(acc[mf][nf][0] + bi0, acc[mf][nf][1] + bi1);
            *(float2*)(C + (size_t)(r0 + 8) * Ntot + c) =
                make_float2(acc[mf][nf][2] + bi0, acc[mf][nf][3] + bi1);
        }
    }
}

// ---------------------------------------------------------------------------
// Highway combine + fused bf16 hi/lo split of new h
// ---------------------------------------------------------------------------
__global__ __launch_bounds__(256)
void highway_kernel(const float* __restrict__ p, float* __restrict__ h,
                    __nv_bfloat16* __restrict__ hhi,
                    __nv_bfloat16* __restrict__ hlo) {
    int idx = blockIdx.x * blockDim.x + threadIdx.x;
    int total = NTOK * (NFILT / 4);
    if (idx >= total) return;
    int m  = idx / (NFILT / 4);
    int j4 = idx % (NFILT / 4);

    const float4 pt = *(const float4*)(p + (size_t)m * (2 * NFILT) + j4 * 4);
    const float4 pg = *(const float4*)(p + (size_t)m * (2 * NFILT) + NFILT + j4 * 4);
    float4 hv = *(float4*)(h + (size_t)m * NFILT + j4 * 4);

    float g;
    g = 1.0f / (1.0f + expf(-pg.x)); hv.x = g * hv.x + (1.0f - g) * fmaxf(pt.x, 0.0f);
    g = 1.0f / (1.0f + expf(-pg.y)); hv.y = g * hv.y + (1.0f - g) * fmaxf(pt.y, 0.0f);
    g = 1.0f / (1.0f + expf(-pg.z)); hv.z = g * hv.z + (1.0f - g) * fmaxf(pt.z, 0.0f);
    g = 1.0f / (1.0f + expf(-pg.w)); hv.w = g * hv.w + (1.0f - g) * fmaxf(pt.w, 0.0f);

    *(float4*)(h + (size_t)m * NFILT + j4 * 4) = hv;

    __nv_bfloat16 h0 = __float2bfloat16(hv.x);
    __nv_bfloat16 h1 = __float2bfloat16(hv.y);
    __nv_bfloat16 h2 = __float2bfloat16(hv.z);
    __nv_bfloat16 h3 = __float2bfloat16(hv.w);
    __nv_bfloat162* hp = (__nv_bfloat162*)(hhi + (size_t)m * NFILT + j4 * 4);
    __nv_bfloat162* lp = (__nv_bfloat162*)(hlo + (size_t)m * NFILT + j4 * 4);
    hp[0] = __halves2bfloat162(h0, h1);
    hp[1] = __halves2bfloat162(h2, h3);
    lp[0] = __halves2bfloat162(__float2bfloat16(hv.x - __bfloat162float(h0)),
                               __float2bfloat16(hv.y - __bfloat162float(h1)));
    lp[1] = __halves2bfloat162(__float2bfloat16(hv.z - __bfloat162float(h2)),
                               __float2bfloat16(hv.w - __bfloat162float(h3)));
}

// ---------------------------------------------------------------------------
// Launch — my-index-3 (= ncu's profiled slot) is the first highway GEMM
// ---------------------------------------------------------------------------
extern "C" void kernel_launch(void* const* d_in, const int* in_sizes, int n_in,
                              void* d_out, int out_size) {
    const int*   chars  = (const int*)d_in[1];
    const float* emb    = (const float*)d_in[2];
    const float* cw[7], *cb[7];
    for (int i = 0; i < 7; i++) {
        cw[i] = (const float*)d_in[3 + 2 * i];
        cb[i] = (const float*)d_in[4 + 2 * i];
    }
    const float* hw_w0  = (const float*)d_in[17];
    const float* hw_b0  = (const float*)d_in[18];
    const float* hw_w1  = (const float*)d_in[19];
    const float* hw_b1  = (const float*)d_in[20];
    const float* proj_w = (const float*)d_in[21];
    const float* proj_b = (const float*)d_in[22];
    float* out = (float*)d_out;

    static float *hbuf = nullptr, *pbuf = nullptr, *wtbuf = nullptr;
    static __nv_bfloat16 *hhi, *hlo, *w0hi, *w0lo, *w1hi, *w1lo, *wphi, *wplo;
    if (!hbuf) {
        cudaGetSymbolAddress((void**)&hbuf,  g_h);
        cudaGetSymbolAddress((void**)&pbuf,  g_p);
        cudaGetSymbolAddress((void**)&wtbuf, g_wt);
        cudaGetSymbolAddress((void**)&hhi,   g_hhi);
        cudaGetSymbolAddress((void**)&hlo,   g_hlo);
        cudaGetSymbolAddress((void**)&w0hi,  g_w0hi);
        cudaGetSymbolAddress((void**)&w0lo,  g_w0lo);
        cudaGetSymbolAddress((void**)&w1hi,  g_w1hi);
        cudaGetSymbolAddress((void**)&w1lo,  g_w1lo);
        cudaGetSymbolAddress((void**)&wphi,  g_wphi);
        cudaGetSymbolAddress((void**)&wplo,  g_wplo);
        cudaFuncSetAttribute(gemm_prj,
                             cudaFuncAttributeMaxDynamicSharedMemorySize,
                             PR_DSMEM);
    }

    dim3 blk(256);
    const int nW  = 2 * NFILT * NFILT;
    const int nWP = PROJ * NFILT;
    auto cvb = [](int n) { return (n / 4 + 255) / 256; };

    dim3 grid_hw(2 * NFILT / 128, NTOK / 128);   // (32, 32) — 1024 CTAs
    dim3 grid_pr(PROJ / 128, NTOK / 128);        // (4, 32)
    int hw_blocks = (NTOK * (NFILT / 4) + 255) / 256;

    // index 0: merged conv-weight transpose
    transpose_all<<<(197120 + 255) / 256, blk>>>(cw[0], cw[1], cw[2], cw[3],
                                                 cw[4], cw[5], cw[6], wtbuf);
    // index 1: w0 split
    cvt_split<<<cvb(nW), blk>>>(hw_w0, w0hi, w0lo, nW / 4);
    // index 2: conv
    conv_kernel<<<NTOK, 256>>>(chars, emb, wtbuf,
                               cb[0], cb[1], cb[2], cb[3], cb[4], cb[5], cb[6],
                               hbuf, hhi, hlo);
    // index 3: highway-0 GEMM (ncu slot) — 128x128 tile, 2 CTAs/SM
    gemm_prj<<<grid_hw, blk, PR_DSMEM>>>(hhi, hlo, w0hi, w0lo, hw_b0,
                                         pbuf, 2 * NFILT);
    // index 4: highway-0 combine
    highway_kernel<<<hw_blocks, blk>>>(pbuf, hbuf, hhi, hlo);
    // index 5: w1 split
    cvt_split<<<cvb(nW), blk>>>(hw_w1, w1hi, w1lo, nW / 4);
    // index 6: highway-1 GEMM
    gemm_prj<<<grid_hw, blk, PR_DSMEM>>>(hhi, hlo, w1hi, w1lo, hw_b1,
                                         pbuf, 2 * NFILT);
    // index 7: highway-1 combine
    highway_kernel<<<hw_blocks, blk>>>(pbuf, hbuf, hhi, hlo);
    // index 8: proj weight split
    cvt_split<<<cvb(nWP), blk>>>(proj_w, wphi, wplo, nWP / 4);
    // index 9: projection
    gemm_prj<<<grid_pr, blk, PR_DSMEM>>>(hhi, hlo, wphi, wplo, proj_b,
                                         out, PROJ);
}

// round 14
// speedup vs baseline: 1.1917x; 1.0658x over previous
#include <cuda_runtime.h>
#include <cuda_bf16.h>
#include <math.h>
#include <stdint.h>

// ---------------------------------------------------------------------------
// ConvTokenEmbedder: char CNN + highway x2 + projection
// Round 14: fused bf16x3 GEMM — load Ahi/Alo/Bhi/Blo once per K-chunk and
//           compute all 3 products from SMEM (L2 traffic x2/3, 64 iters).
//           Rest = round-13 (2712us) verbatim.
// ---------------------------------------------------------------------------

#define NTOK   4096
#define NFILT  2048
#define PROJ   512
#define MAXC   50
#define CDIM   16
#define KDIM   2048

typedef unsigned long long u64;

// Scratch
__device__ float g_h[NTOK * NFILT];
__device__ float g_p[NTOK * 2 * NFILT];
__device__ float g_wt[197120];
__device__ __nv_bfloat16 g_hhi[NTOK * NFILT];
__device__ __nv_bfloat16 g_hlo[NTOK * NFILT];
__device__ __nv_bfloat16 g_w0hi[2 * NFILT * NFILT];
__device__ __nv_bfloat16 g_w0lo[2 * NFILT * NFILT];
__device__ __nv_bfloat16 g_w1hi[2 * NFILT * NFILT];
__device__ __nv_bfloat16 g_w1lo[2 * NFILT * NFILT];
__device__ __nv_bfloat16 g_wphi[PROJ * NFILT];
__device__ __nv_bfloat16 g_wplo[PROJ * NFILT];

#define WT_O0 0
#define WT_O1 512
#define WT_O2 1536
#define WT_O3 4608
#define WT_O4 12800
#define WT_O5 33280
#define WT_O6 82432

// ---------------------------------------------------------------------------
// packed f32x2 helpers
// ---------------------------------------------------------------------------
__device__ __forceinline__ u64 fma_x2(u64 a, u64 b, u64 c) {
    u64 d;
    asm("fma.rn.f32x2 %0, %1, %2, %3;" : "=l"(d) : "l"(a), "l"(b), "l"(c));
    return d;
}
__device__ __forceinline__ u64 pack2(float lo, float hi) {
    u64 d;
    asm("mov.b64 %0, {%1, %2};" : "=l"(d) : "f"(lo), "f"(hi));
    return d;
}
__device__ __forceinline__ float2 unpack2(u64 v) {
    float lo, hi;
    asm("mov.b64 {%0, %1}, %2;" : "=f"(lo), "=f"(hi) : "l"(v));
    return make_float2(lo, hi);
}

// ---------------------------------------------------------------------------
// Merged weight transpose
// ---------------------------------------------------------------------------
__global__ __launch_bounds__(256)
void transpose_all(const float* __restrict__ w0, const float* __restrict__ w1,
                   const float* __restrict__ w2, const float* __restrict__ w3,
                   const float* __restrict__ w4, const float* __restrict__ w5,
                   const float* __restrict__ w6, float* __restrict__ out) {
    int idx = blockIdx.x * blockDim.x + threadIdx.x;
    if (idx >= 197120) return;
    const float* src;
    int base, nf, cw, local;
    if      (idx < 1536)  { if (idx < 512) { src = w0; base = WT_O0; nf = 32;  cw = 16; local = idx; }
                            else           { src = w1; base = WT_O1; nf = 32;  cw = 32; local = idx - 512; } }
    else if (idx < 4608)  { src = w2; base = WT_O2; nf = 64;   cw = 48;  local = idx - 1536; }
    else if (idx < 12800) { src = w3; base = WT_O3; nf = 128;  cw = 64;  local = idx - 4608; }
    else if (idx < 33280) { src = w4; base = WT_O4; nf = 256;  cw = 80;  local = idx - 12800; }
    else if (idx < 82432) { src = w5; base = WT_O5; nf = 512;  cw = 96;  local = idx - 33280; }
    else                  { src = w6; base = WT_O6; nf = 1024; cw = 112; local = idx - 82432; }
    int f = local / cw;
    int r = local - f * cw;
    out[base + r * nf + f] = src[local];
}

// ---------------------------------------------------------------------------
// Conv stage — packed two-chunk accumulation via fma.rn.f32x2 (round 5 exact)
// ---------------------------------------------------------------------------
#define XS2_O1 0
#define XS2_O2 400
#define XS2_O3 816
#define XS2_O4 1232
#define XS2_O5 1664
#define XS2_O6 2096
#define XS2_O7 2544
#define XS2_TOT 2992

template <int W>
__device__ __forceinline__ float conv_max2(const u64* __restrict__ xs2,
                                           const float* __restrict__ wt,
                                           int nf, int f, float bias) {
    constexpr int NT = 51 - W;
    constexpr int TC = (NT + 1) / 2;
    constexpr int J  = TC + W - 1;
    u64 acc[TC];
#pragma unroll
    for (int t = 0; t < TC; t++) acc[t] = 0ULL;

#pragma unroll 2
    for (int c = 0; c < CDIM; c++) {
        u64 w2[W];
#pragma unroll
        for (int k = 0; k < W; k++) {
            float w = wt[(c * W + k) * nf + f];
            w2[k] = pack2(w, w);
        }
#pragma unroll
        for (int j = 0; j < J; j++) {
            u64 xv = xs2[c * J + j];
#pragma unroll
            for (int k = 0; k < W; k++) {
                int t = j - k;
                if (t >= 0 && t < TC) acc[t] = fma_x2(xv, w2[k], acc[t]);
            }
        }
    }
    float best = -3.4e38f;
#pragma unroll
    for (int t = 0; t < TC; t++) {
        float2 v = unpack2(acc[t]);
        best = fmaxf(best, fmaxf(v.x, v.y));
    }
    return fmaxf(best + bias, 0.0f);
}

__device__ __forceinline__ void store_split(float r, float* h,
                                            __nv_bfloat16* hi,
                                            __nv_bfloat16* lo, size_t o) {
    h[o] = r;
    __nv_bfloat16 hh = __float2bfloat16(r);
    hi[o] = hh;
    lo[o] = __float2bfloat16(r - __bfloat162float(hh));
}

__global__ __launch_bounds__(256)
void conv_kernel(const int*   __restrict__ chars,
                 const float* __restrict__ emb,
                 const float* __restrict__ wt,
                 const float* __restrict__ b0, const float* __restrict__ b1,
                 const float* __restrict__ b2, const float* __restrict__ b3,
                 const float* __restrict__ b4, const float* __restrict__ b5,
                 const float* __restrict__ b6,
                 float* __restrict__ h,
                 __nv_bfloat16* __restrict__ hhi,
                 __nv_bfloat16* __restrict__ hlo) {
    __shared__ float xs[CDIM * 51];
    __shared__ int   chs[MAXC];
    __shared__ u64   xs2[XS2_TOT];

    const int n   = blockIdx.x;
    const int tid = threadIdx.x;

    if (tid < MAXC) chs[tid] = chars[n * MAXC + tid];
    __syncthreads();
    for (int idx = tid; idx < MAXC * CDIM; idx += 256) {
        int t = idx >> 4;
        int c = idx & 15;
        xs[c * 51 + t] = emb[chs[t] * CDIM + c];
    }
    __syncthreads();

    {
        const int offs[7] = {XS2_O1, XS2_O2, XS2_O3, XS2_O4, XS2_O5, XS2_O6, XS2_O7};
        const int Js[7]   = {25, 26, 26, 27, 27, 28, 28};
        const int OFFs[7] = {25, 24, 24, 23, 23, 22, 22};
#pragma unroll
        for (int w = 0; w < 7; w++) {
            const int J = Js[w], OFF = OFFs[w];
            u64* dst = xs2 + offs[w];
            for (int idx = tid; idx < CDIM * J; idx += 256) {
                int c = idx / J;
                int j = idx - c * J;
                dst[idx] = pack2(xs[c * 51 + j], xs[c * 51 + OFF + j]);
            }
        }
    }
    __syncthreads();

    const size_t rowo = (size_t)n * NFILT;
    {
        int f = tid;
        float r;
        if (f < 32)        r = conv_max2<1>(xs2 + XS2_O1, wt + WT_O0, 32,  f,       b0[f]);
        else if (f < 64)   r = conv_max2<2>(xs2 + XS2_O2, wt + WT_O1, 32,  f - 32,  b1[f - 32]);
        else if (f < 128)  r = conv_max2<3>(xs2 + XS2_O3, wt + WT_O2, 64,  f - 64,  b2[f - 64]);
        else               r = conv_max2<4>(xs2 + XS2_O4, wt + WT_O3, 128, f - 128, b3[f - 128]);
        store_split(r, h, hhi, hlo, rowo + f);
    }
    {
        int f = tid;
        float r = conv_max2<5>(xs2 + XS2_O5, wt + WT_O4, 256, f, b4[f]);
        store_split(r, h, hhi, hlo, rowo + 256 + f);
    }
#pragma unroll
    for (int i = 0; i < 2; i++) {
        int f = tid + i * 256;
        float r = conv_max2<6>(xs2 + XS2_O6, wt + WT_O5, 512, f, b5[f]);
        store_split(r, h, hhi, hlo, rowo + 512 + f);
    }
#pragma unroll
    for (int i = 0; i < 4; i++) {
        int f = tid + i * 256;
        float r = conv_max2<7>(xs2 + XS2_O7, wt + WT_O6, 1024, f, b6[f]);
        store_split(r, h, hhi, hlo, rowo + 1024 + f);
    }
}

// ---------------------------------------------------------------------------
// fp32 -> (bf16 hi, bf16 lo) split (weights)
// ---------------------------------------------------------------------------
__global__ __launch_bounds__(256)
void cvt_split(const float* __restrict__ x,
               __nv_bfloat16* __restrict__ hi,
               __nv_bfloat16* __restrict__ lo, int n4) {
    int i = blockIdx.x * blockDim.x + threadIdx.x;
    if (i >= n4) return;
    float4 v = ((const float4*)x)[i];
    __nv_bfloat16 h0 = __float2bfloat16(v.x);
    __nv_bfloat16 h1 = __float2bfloat16(v.y);
    __nv_bfloat16 h2 = __float2bfloat16(v.z);
    __nv_bfloat16 h3 = __float2bfloat16(v.w);
    __nv_bfloat162* hp = (__nv_bfloat162*)hi + i * 2;
    __nv_bfloat162* lp = (__nv_bfloat162*)lo + i * 2;
    hp[0] = __halves2bfloat162(h0, h1);
    hp[1] = __halves2bfloat162(h2, h3);
    lp[0] = __halves2bfloat162(__float2bfloat16(v.x - __bfloat162float(h0)),
                               __float2bfloat16(v.y - __bfloat162float(h1)));
    lp[1] = __halves2bfloat162(__float2bfloat16(v.z - __bfloat162float(h2)),
                               __float2bfloat16(v.w - __bfloat162float(h3)));
}

// ---------------------------------------------------------------------------
// mma helpers
// ---------------------------------------------------------------------------
#define GSTR 40

__device__ __forceinline__ void ldm_x4(uint32_t addr, uint32_t& r0, uint32_t& r1,
                                       uint32_t& r2, uint32_t& r3) {
    asm volatile("ldmatrix.sync.aligned.m8n8.x4.shared.b16 {%0,%1,%2,%3}, [%4];"
                 : "=r"(r0), "=r"(r1), "=r"(r2), "=r"(r3) : "r"(addr));
}
__device__ __forceinline__ void mma16816(float* c, const uint32_t* a,
                                         uint32_t b0, uint32_t b1) {
    asm volatile(
        "mma.sync.aligned.m16n8k16.row.col.f32.bf16.bf16.f32 "
        "{%0,%1,%2,%3}, {%4,%5,%6,%7}, {%8,%9}, {%0,%1,%2,%3};"
        : "+f"(c[0]), "+f"(c[1]), "+f"(c[2]), "+f"(c[3])
        : "r"(a[0]), "r"(a[1]), "r"(a[2]), "r"(a[3]), "r"(b0), "r"(b1));
}
__device__ __forceinline__ void cp16(uint32_t s, const void* g) {
    asm volatile("cp.async.cg.shared.global [%0], [%1], 16;" :: "r"(s), "l"(g));
}
#define CP_COMMIT() asm volatile("cp.async.commit_group;" ::: "memory")
#define CP_WAIT(n)  asm volatile("cp.async.wait_group %0;" :: "n"(n) : "memory")

__device__ __forceinline__ uint32_t smem_u32(const void* p) {
    uint32_t a;
    asm("{ .reg .u64 t; cvta.to.shared.u64 t, %1; cvt.u32.u64 %0, t; }"
        : "=r"(a) : "l"(p));
    return a;
}

// ---------------------------------------------------------------------------
// Fused bf16x3 GEMM: CTA 128x128, 256 threads, warp 32x64, BK=32,
// 2 stages of {Ahi, Alo, Bhi, Blo} (40KB/stage), 64 K-iterations.
// All 3 products (hi*hi, lo*hi, hi*lo) computed from one SMEM load.
// ---------------------------------------------------------------------------
#define MSTG  10240                     // one matrix per stage (128*40*2)
#define FSTG  (4 * MSTG)                // full stage: 40960
#define F_DSMEM (2 * FSTG)              // 81920
#define FITERS (KDIM / 32)              // 64

__global__ __launch_bounds__(256, 2)
void gemm_f3(const __nv_bfloat16* __restrict__ Ahi,
             const __nv_bfloat16* __restrict__ Alo,
             const __nv_bfloat16* __restrict__ Bhi,
             const __nv_bfloat16* __restrict__ Blo,
             const float* __restrict__ bias,
             float* __restrict__ C, int Ntot) {
    extern __shared__ __nv_bfloat16 sm[];
    const uint32_t sbase = smem_u32(sm);

    const int tid  = threadIdx.x;
    const int lane = tid & 31;
    const int warp = tid >> 5;
    const int wm   = warp & 3;
    const int wn   = warp >> 2;
    const int bm   = blockIdx.y * 128;
    const int bn   = blockIdx.x * 128;

    const int lrow = tid >> 1;          // 0..127
    const int lc0  = (tid & 1) * 2;     // chunk pair {0,1} or {2,3}

    const int q2 = lane >> 3;
    const int lr = lane & 7;
    const int aMrow = wm * 32 + (q2 & 1) * 8 + lr;
    const int aKoff = (q2 >> 1) * 8;
    const int bNrow = wn * 64 + (q2 >> 1) * 8 + lr;
    const int bKoff = (q2 & 1) * 8;

    float acc[2][8][4];
#pragma unroll
    for (int i = 0; i < 2; i++)
#pragma unroll
        for (int j = 0; j < 8; j++)
#pragma unroll
            for (int r = 0; r < 4; r++) acc[i][j][r] = 0.0f;

    // load one K-chunk of all 4 matrices into stage s
    auto issue = [&](int it, int s) {
        const int kloc = it * 32;
        const uint32_t st = sbase + (uint32_t)s * FSTG;
        const size_t ga = (size_t)(bm + lrow) * KDIM + kloc;
        const size_t gb = (size_t)(bn + lrow) * KDIM + kloc;
#pragma unroll
        for (int j = 0; j < 2; j++) {
            const int c = lc0 + j;
            const uint32_t so = (uint32_t)(lrow * GSTR + c * 8) * 2;
            cp16(st + 0 * MSTG + so, Ahi + ga + c * 8);
            cp16(st + 1 * MSTG + so, Alo + ga + c * 8);
            cp16(st + 2 * MSTG + so, Bhi + gb + c * 8);
            cp16(st + 3 * MSTG + so, Blo + gb + c * 8);
        }
    };

    issue(0, 0);
    CP_COMMIT();

    for (int it = 0; it < FITERS; it++) {
        CP_WAIT(0);
        __syncthreads();
        if (it + 1 < FITERS) issue(it + 1, (it + 1) & 1);
        CP_COMMIT();

        const uint32_t st = sbase + (uint32_t)(it & 1) * FSTG;
#pragma unroll
        for (int q = 0; q < 2; q++) {
            uint32_t a0[2][4], a1[2][4];
#pragma unroll
            for (int mf = 0; mf < 2; mf++) {
                const uint32_t ao =
                    (uint32_t)(((aMrow + mf * 16) * GSTR + q * 16 + aKoff) * 2);
                ldm_x4(st + 0 * MSTG + ao, a0[mf][0], a0[mf][1], a0[mf][2], a0[mf][3]);
                ldm_x4(st + 1 * MSTG + ao, a1[mf][0], a1[mf][1], a1[mf][2], a1[mf][3]);
            }
            uint32_t b[4][4];
            // Bhi: hi*hi and lo*hi
#pragma unroll
            for (int p = 0; p < 4; p++) {
                const uint32_t bo =
                    (uint32_t)(((bNrow + p * 16) * GSTR + q * 16 + bKoff) * 2);
                ldm_x4(st + 2 * MSTG + bo, b[p][0], b[p][1], b[p][2], b[p][3]);
            }
#pragma unroll
            for (int mf = 0; mf < 2; mf++)
#pragma unroll
                for (int nf = 0; nf < 8; nf++) {
                    const uint32_t bb0 = b[nf >> 1][(nf & 1) * 2 + 0];
                    const uint32_t bb1 = b[nf >> 1][(nf & 1) * 2 + 1];
                    mma16816(acc[mf][nf], a0[mf], bb0, bb1);
                    mma16816(acc[mf][nf], a1[mf], bb0, bb1);
                }
            // Blo: hi*lo
#pragma unroll
            for (int p = 0; p < 4; p++) {
                const uint32_t bo =
                    (uint32_t)(((bNrow + p * 16) * GSTR + q * 16 + bKoff) * 2);
                ldm_x4(st + 3 * MSTG + bo, b[p][0], b[p][1], b[p][2], b[p][3]);
            }
#pragma unroll
            for (int mf = 0; mf < 2; mf++)
#pragma unroll
                for (int nf = 0; nf < 8; nf++)
                    mma16816(acc[mf][nf], a0[mf],
                             b[nf >> 1][(nf & 1) * 2 + 0],
                             b[nf >> 1][(nf & 1) * 2 + 1]);
        }
    }

    const int mbase = bm + wm * 32 + (lane >> 2);
    const int nbase = bn + wn * 64 + (lane & 3) * 2;
#pragma unroll
    for (int mf = 0; mf < 2; mf++) {
#pragma unroll
        for (int nf = 0; nf < 8; nf++) {
            const int c = nbase + nf * 8;
            const float bi0 = __ldg(bias + c);
            const float bi1 = __ldg(bias + c + 1);
            const int r0 = mbase + mf * 16;
            *(float2*)(C + (size_t)r0 * Ntot + c) =
                make_float2(acc[mf][nf][0] + bi0, acc[mf][nf][1] + bi1);
            *(float2*)(C + (size_t)(r0 + 8) * Ntot + c) =
                make_float2(acc[mf][nf][2] + bi0, acc[mf][nf][3] + bi1);
        }
    }
}

// ---------------------------------------------------------------------------
// Highway combine + fused bf16 hi/lo split of new h
// ---------------------------------------------------------------------------
__global__ __launch_bounds__(256)
void highway_kernel(const float* __restrict__ p, float* __restrict__ h,
                    __nv_bfloat16* __restrict__ hhi,
                    __nv_bfloat16* __restrict__ hlo) {
    int idx = blockIdx.x * blockDim.x + threadIdx.x;
    int total = NTOK * (NFILT / 4);
    if (idx >= total) return;
    int m  = idx / (NFILT / 4);
    int j4 = idx % (NFILT / 4);

    const float4 pt = *(const float4*)(p + (size_t)m * (2 * NFILT) + j4 * 4);
    const float4 pg = *(const float4*)(p + (size_t)m * (2 * NFILT) + NFILT + j4 * 4);
    float4 hv = *(float4*)(h + (size_t)m * NFILT + j4 * 4);

    float g;
    g = 1.0f / (1.0f + expf(-pg.x)); hv.x = g * hv.x + (1.0f - g) * fmaxf(pt.x, 0.0f);
    g = 1.0f / (1.0f + expf(-pg.y)); hv.y = g * hv.y + (1.0f - g) * fmaxf(pt.y, 0.0f);
    g = 1.0f / (1.0f + expf(-pg.z)); hv.z = g * hv.z + (1.0f - g) * fmaxf(pt.z, 0.0f);
    g = 1.0f / (1.0f + expf(-pg.w)); hv.w = g * hv.w + (1.0f - g) * fmaxf(pt.w, 0.0f);

    *(float4*)(h + (size_t)m * NFILT + j4 * 4) = hv;

    __nv_bfloat16 h0 = __float2bfloat16(hv.x);
    __nv_bfloat16 h1 = __float2bfloat16(hv.y);
    __nv_bfloat16 h2 = __float2bfloat16(hv.z);
    __nv_bfloat16 h3 = __float2bfloat16(hv.w);
    __nv_bfloat162* hp = (__nv_bfloat162*)(hhi + (size_t)m * NFILT + j4 * 4);
    __nv_bfloat162* lp = (__nv_bfloat162*)(hlo + (size_t)m * NFILT + j4 * 4);
    hp[0] = __halves2bfloat162(h0, h1);
    hp[1] = __halves2bfloat162(h2, h3);
    lp[0] = __halves2bfloat162(__float2bfloat16(hv.x - __bfloat162float(h0)),
                               __float2bfloat16(hv.y - __bfloat162float(h1)));
    lp[1] = __halves2bfloat162(__float2bfloat16(hv.z - __bfloat162float(h2)),
                               __float2bfloat16(hv.w - __bfloat162float(h3)));
}

// ---------------------------------------------------------------------------
// Launch — my-index-3 (= ncu's profiled slot) is the first highway GEMM
// ---------------------------------------------------------------------------
extern "C" void kernel_launch(void* const* d_in, const int* in_sizes, int n_in,
                              void* d_out, int out_size) {
    const int*   chars  = (const int*)d_in[1];
    const float* emb    = (const float*)d_in[2];
    const float* cw[7], *cb[7];
    for (int i = 0; i < 7; i++) {
        cw[i] = (const float*)d_in[3 + 2 * i];
        cb[i] = (const float*)d_in[4 + 2 * i];
    }
    const float* hw_w0  = (const float*)d_in[17];
    const float* hw_b0  = (const float*)d_in[18];
    const float* hw_w1  = (const float*)d_in[19];
    const float* hw_b1  = (const float*)d_in[20];
    const float* proj_w = (const float*)d_in[21];
    const float* proj_b = (const float*)d_in[22];
    float* out = (float*)d_out;

    static float *hbuf = nullptr, *pbuf = nullptr, *wtbuf = nullptr;
    static __nv_bfloat16 *hhi, *hlo, *w0hi, *w0lo, *w1hi, *w1lo, *wphi, *wplo;
    if (!hbuf) {
        cudaGetSymbolAddress((void**)&hbuf,  g_h);
        cudaGetSymbolAddress((void**)&pbuf,  g_p);
        cudaGetSymbolAddress((void**)&wtbuf, g_wt);
        cudaGetSymbolAddress((void**)&hhi,   g_hhi);
        cudaGetSymbolAddress((void**)&hlo,   g_hlo);
        cudaGetSymbolAddress((void**)&w0hi,  g_w0hi);
        cudaGetSymbolAddress((void**)&w0lo,  g_w0lo);
        cudaGetSymbolAddress((void**)&w1hi,  g_w1hi);
        cudaGetSymbolAddress((void**)&w1lo,  g_w1lo);
        cudaGetSymbolAddress((void**)&wphi,  g_wphi);
        cudaGetSymbolAddress((void**)&wplo,  g_wplo);
        cudaFuncSetAttribute(gemm_f3,
                             cudaFuncAttributeMaxDynamicSharedMemorySize,
                             F_DSMEM);
    }

    dim3 blk(256);
    const int nW  = 2 * NFILT * NFILT;
    const int nWP = PROJ * NFILT;
    auto cvb = [](int n) { return (n / 4 + 255) / 256; };

    dim3 grid_hw(2 * NFILT / 128, NTOK / 128);   // (32, 32)
    dim3 grid_pr(PROJ / 128, NTOK / 128);        // (4, 32)
    int hw_blocks = (NTOK * (NFILT / 4) + 255) / 256;

    // index 0: merged conv-weight transpose
    transpose_all<<<(197120 + 255) / 256, blk>>>(cw[0], cw[1], cw[2], cw[3],
                                                 cw[4], cw[5], cw[6], wtbuf);
    // index 1: w0 split
    cvt_split<<<cvb(nW), blk>>>(hw_w0, w0hi, w0lo, nW / 4);
    // index 2: conv
    conv_kernel<<<NTOK, 256>>>(chars, emb, wtbuf,
                               cb[0], cb[1], cb[2], cb[3], cb[4], cb[5], cb[6],
                               hbuf, hhi, hlo);
    // index 3: highway-0 GEMM (ncu slot)
    gemm_f3<<<grid_hw, blk, F_DSMEM>>>(hhi, hlo, w0hi, w0lo, hw_b0,
                                       pbuf, 2 * NFILT);
    // index 4: highway-0 combine
    highway_kernel<<<hw_blocks, blk>>>(pbuf, hbuf, hhi, hlo);
    // index 5: w1 split
    cvt_split<<<cvb(nW), blk>>>(hw_w1, w1hi, w1lo, nW / 4);
    // index 6: highway-1 GEMM
    gemm_f3<<<grid_hw, blk, F_DSMEM>>>(hhi, hlo, w1hi, w1lo, hw_b1,
                                       pbuf, 2 * NFILT);
    // index 7: highway-1 combine
    highway_kernel<<<hw_blocks, blk>>>(pbuf, hbuf, hhi, hlo);
    // index 8: proj weight split
    cvt_split<<<cvb(nWP), blk>>>(proj_w, wphi, wplo, nWP / 4);
    // index 9: projection
    gemm_f3<<<grid_pr, blk, F_DSMEM>>>(hhi, hlo, wphi, wplo, proj_b,
                                       out, PROJ);
}

// round 15
// speedup vs baseline: 1.1993x; 1.0064x over previous
#include <cuda_runtime.h>
#include <cuda_bf16.h>
#include <math.h>
#include <stdint.h>

// ---------------------------------------------------------------------------
// ConvTokenEmbedder: char CNN + highway x2 + projection
// Round 15: (a) weight-split kernels forked onto a side stream and hidden
//           under the conv; (b) gemm_f3 q-loop loads Bhi/Blo into separate
//           registers (kills the WAR hazard between product groups).
//           Rest = round-14 (2544us) verbatim.
// ---------------------------------------------------------------------------

#define NTOK   4096
#define NFILT  2048
#define PROJ   512
#define MAXC   50
#define CDIM   16
#define KDIM   2048

typedef unsigned long long u64;

// Scratch
__device__ float g_h[NTOK * NFILT];
__device__ float g_p[NTOK * 2 * NFILT];
__device__ float g_wt[197120];
__device__ __nv_bfloat16 g_hhi[NTOK * NFILT];
__device__ __nv_bfloat16 g_hlo[NTOK * NFILT];
__device__ __nv_bfloat16 g_w0hi[2 * NFILT * NFILT];
__device__ __nv_bfloat16 g_w0lo[2 * NFILT * NFILT];
__device__ __nv_bfloat16 g_w1hi[2 * NFILT * NFILT];
__device__ __nv_bfloat16 g_w1lo[2 * NFILT * NFILT];
__device__ __nv_bfloat16 g_wphi[PROJ * NFILT];
__device__ __nv_bfloat16 g_wplo[PROJ * NFILT];

#define WT_O0 0
#define WT_O1 512
#define WT_O2 1536
#define WT_O3 4608
#define WT_O4 12800
#define WT_O5 33280
#define WT_O6 82432

// ---------------------------------------------------------------------------
// packed f32x2 helpers
// ---------------------------------------------------------------------------
__device__ __forceinline__ u64 fma_x2(u64 a, u64 b, u64 c) {
    u64 d;
    asm("fma.rn.f32x2 %0, %1, %2, %3;" : "=l"(d) : "l"(a), "l"(b), "l"(c));
    return d;
}
__device__ __forceinline__ u64 pack2(float lo, float hi) {
    u64 d;
    asm("mov.b64 %0, {%1, %2};" : "=l"(d) : "f"(lo), "f"(hi));
    return d;
}
__device__ __forceinline__ float2 unpack2(u64 v) {
    float lo, hi;
    asm("mov.b64 {%0, %1}, %2;" : "=f"(lo), "=f"(hi) : "l"(v));
    return make_float2(lo, hi);
}

// ---------------------------------------------------------------------------
// Merged weight transpose
// ---------------------------------------------------------------------------
__global__ __launch_bounds__(256)
void transpose_all(const float* __restrict__ w0, const float* __restrict__ w1,
                   const float* __restrict__ w2, const float* __restrict__ w3,
                   const float* __restrict__ w4, const float* __restrict__ w5,
                   const float* __restrict__ w6, float* __restrict__ out) {
    int idx = blockIdx.x * blockDim.x + threadIdx.x;
    if (idx >= 197120) return;
    const float* src;
    int base, nf, cw, local;
    if      (idx < 1536)  { if (idx < 512) { src = w0; base = WT_O0; nf = 32;  cw = 16; local = idx; }
                            else           { src = w1; base = WT_O1; nf = 32;  cw = 32; local = idx - 512; } }
    else if (idx < 4608)  { src = w2; base = WT_O2; nf = 64;   cw = 48;  local = idx - 1536; }
    else if (idx < 12800) { src = w3; base = WT_O3; nf = 128;  cw = 64;  local = idx - 4608; }
    else if (idx < 33280) { src = w4; base = WT_O4; nf = 256;  cw = 80;  local = idx - 12800; }
    else if (idx < 82432) { src = w5; base = WT_O5; nf = 512;  cw = 96;  local = idx - 33280; }
    else                  { src = w6; base = WT_O6; nf = 1024; cw = 112; local = idx - 82432; }
    int f = local / cw;
    int r = local - f * cw;
    out[base + r * nf + f] = src[local];
}

// ---------------------------------------------------------------------------
// Conv stage — packed two-chunk accumulation via fma.rn.f32x2 (round 5 exact)
// ---------------------------------------------------------------------------
#define XS2_O1 0
#define XS2_O2 400
#define XS2_O3 816
#define XS2_O4 1232
#define XS2_O5 1664
#define XS2_O6 2096
#define XS2_O7 2544
#define XS2_TOT 2992

template <int W>
__device__ __forceinline__ float conv_max2(const u64* __restrict__ xs2,
                                           const float* __restrict__ wt,
                                           int nf, int f, float bias) {
    constexpr int NT = 51 - W;
    constexpr int TC = (NT + 1) / 2;
    constexpr int J  = TC + W - 1;
    u64 acc[TC];
#pragma unroll
    for (int t = 0; t < TC; t++) acc[t] = 0ULL;

#pragma unroll 2
    for (int c = 0; c < CDIM; c++) {
        u64 w2[W];
#pragma unroll
        for (int k = 0; k < W; k++) {
            float w = wt[(c * W + k) * nf + f];
            w2[k] = pack2(w, w);
        }
#pragma unroll
        for (int j = 0; j < J; j++) {
            u64 xv = xs2[c * J + j];
#pragma unroll
            for (int k = 0; k < W; k++) {
                int t = j - k;
                if (t >= 0 && t < TC) acc[t] = fma_x2(xv, w2[k], acc[t]);
            }
        }
    }
    float best = -3.4e38f;
#pragma unroll
    for (int t = 0; t < TC; t++) {
        float2 v = unpack2(acc[t]);
        best = fmaxf(best, fmaxf(v.x, v.y));
    }
    return fmaxf(best + bias, 0.0f);
}

__device__ __forceinline__ void store_split(float r, float* h,
                                            __nv_bfloat16* hi,
                                            __nv_bfloat16* lo, size_t o) {
    h[o] = r;
    __nv_bfloat16 hh = __float2bfloat16(r);
    hi[o] = hh;
    lo[o] = __float2bfloat16(r - __bfloat162float(hh));
}

__global__ __launch_bounds__(256)
void conv_kernel(const int*   __restrict__ chars,
                 const float* __restrict__ emb,
                 const float* __restrict__ wt,
                 const float* __restrict__ b0, const float* __restrict__ b1,
                 const float* __restrict__ b2, const float* __restrict__ b3,
                 const float* __restrict__ b4, const float* __restrict__ b5,
                 const float* __restrict__ b6,
                 float* __restrict__ h,
                 __nv_bfloat16* __restrict__ hhi,
                 __nv_bfloat16* __restrict__ hlo) {
    __shared__ float xs[CDIM * 51];
    __shared__ int   chs[MAXC];
    __shared__ u64   xs2[XS2_TOT];

    const int n   = blockIdx.x;
    const int tid = threadIdx.x;

    if (tid < MAXC) chs[tid] = chars[n * MAXC + tid];
    __syncthreads();
    for (int idx = tid; idx < MAXC * CDIM; idx += 256) {
        int t = idx >> 4;
        int c = idx & 15;
        xs[c * 51 + t] = emb[chs[t] * CDIM + c];
    }
    __syncthreads();

    {
        const int offs[7] = {XS2_O1, XS2_O2, XS2_O3, XS2_O4, XS2_O5, XS2_O6, XS2_O7};
        const int Js[7]   = {25, 26, 26, 27, 27, 28, 28};
        const int OFFs[7] = {25, 24, 24, 23, 23, 22, 22};
#pragma unroll
        for (int w = 0; w < 7; w++) {
            const int J = Js[w], OFF = OFFs[w];
            u64* dst = xs2 + offs[w];
            for (int idx = tid; idx < CDIM * J; idx += 256) {
                int c = idx / J;
                int j = idx - c * J;
                dst[idx] = pack2(xs[c * 51 + j], xs[c * 51 + OFF + j]);
            }
        }
    }
    __syncthreads();

    const size_t rowo = (size_t)n * NFILT;
    {
        int f = tid;
        float r;
        if (f < 32)        r = conv_max2<1>(xs2 + XS2_O1, wt + WT_O0, 32,  f,       b0[f]);
        else if (f < 64)   r = conv_max2<2>(xs2 + XS2_O2, wt + WT_O1, 32,  f - 32,  b1[f - 32]);
        else if (f < 128)  r = conv_max2<3>(xs2 + XS2_O3, wt + WT_O2, 64,  f - 64,  b2[f - 64]);
        else               r = conv_max2<4>(xs2 + XS2_O4, wt + WT_O3, 128, f - 128, b3[f - 128]);
        store_split(r, h, hhi, hlo, rowo + f);
    }
    {
        int f = tid;
        float r = conv_max2<5>(xs2 + XS2_O5, wt + WT_O4, 256, f, b4[f]);
        store_split(r, h, hhi, hlo, rowo + 256 + f);
    }
#pragma unroll
    for (int i = 0; i < 2; i++) {
        int f = tid + i * 256;
        float r = conv_max2<6>(xs2 + XS2_O6, wt + WT_O5, 512, f, b5[f]);
        store_split(r, h, hhi, hlo, rowo + 512 + f);
    }
#pragma unroll
    for (int i = 0; i < 4; i++) {
        int f = tid + i * 256;
        float r = conv_max2<7>(xs2 + XS2_O7, wt + WT_O6, 1024, f, b6[f]);
        store_split(r, h, hhi, hlo, rowo + 1024 + f);
    }
}

// ---------------------------------------------------------------------------
// fp32 -> (bf16 hi, bf16 lo) split (weights)
// ---------------------------------------------------------------------------
__global__ __launch_bounds__(256)
void cvt_split(const float* __restrict__ x,
               __nv_bfloat16* __restrict__ hi,
               __nv_bfloat16* __restrict__ lo, int n4) {
    int i = blockIdx.x * blockDim.x + threadIdx.x;
    if (i >= n4) return;
    float4 v = ((const float4*)x)[i];
    __nv_bfloat16 h0 = __float2bfloat16(v.x);
    __nv_bfloat16 h1 = __float2bfloat16(v.y);
    __nv_bfloat16 h2 = __float2bfloat16(v.z);
    __nv_bfloat16 h3 = __float2bfloat16(v.w);
    __nv_bfloat162* hp = (__nv_bfloat162*)hi + i * 2;
    __nv_bfloat162* lp = (__nv_bfloat162*)lo + i * 2;
    hp[0] = __halves2bfloat162(h0, h1);
    hp[1] = __halves2bfloat162(h2, h3);
    lp[0] = __halves2bfloat162(__float2bfloat16(v.x - __bfloat162float(h0)),
                               __float2bfloat16(v.y - __bfloat162float(h1)));
    lp[1] = __halves2bfloat162(__float2bfloat16(v.z - __bfloat162float(h2)),
                               __float2bfloat16(v.w - __bfloat162float(h3)));
}

// ---------------------------------------------------------------------------
// mma helpers
// ---------------------------------------------------------------------------
#define GSTR 40

__device__ __forceinline__ void ldm_x4(uint32_t addr, uint32_t& r0, uint32_t& r1,
                                       uint32_t& r2, uint32_t& r3) {
    asm volatile("ldmatrix.sync.aligned.m8n8.x4.shared.b16 {%0,%1,%2,%3}, [%4];"
                 : "=r"(r0), "=r"(r1), "=r"(r2), "=r"(r3) : "r"(addr));
}
__device__ __forceinline__ void mma16816(float* c, const uint32_t* a,
                                         uint32_t b0, uint32_t b1) {
    asm volatile(
        "mma.sync.aligned.m16n8k16.row.col.f32.bf16.bf16.f32 "
        "{%0,%1,%2,%3}, {%4,%5,%6,%7}, {%8,%9}, {%0,%1,%2,%3};"
        : "+f"(c[0]), "+f"(c[1]), "+f"(c[2]), "+f"(c[3])
        : "r"(a[0]), "r"(a[1]), "r"(a[2]), "r"(a[3]), "r"(b0), "r"(b1));
}
__device__ __forceinline__ void cp16(uint32_t s, const void* g) {
    asm volatile("cp.async.cg.shared.global [%0], [%1], 16;" :: "r"(s), "l"(g));
}
#define CP_COMMIT() asm volatile("cp.async.commit_group;" ::: "memory")
#define CP_WAIT(n)  asm volatile("cp.async.wait_group %0;" :: "n"(n) : "memory")

__device__ __forceinline__ uint32_t smem_u32(const void* p) {
    uint32_t a;
    asm("{ .reg .u64 t; cvta.to.shared.u64 t, %1; cvt.u32.u64 %0, t; }"
        : "=r"(a) : "l"(p));
    return a;
}

// ---------------------------------------------------------------------------
// Fused bf16x3 GEMM: CTA 128x128, 256 threads, warp 32x64, BK=32,
// 2 stages of {Ahi, Alo, Bhi, Blo}; Bhi/Blo in separate registers (no WAR).
// ---------------------------------------------------------------------------
#define MSTG  10240
#define FSTG  (4 * MSTG)
#define F_DSMEM (2 * FSTG)              // 81920
#define FITERS (KDIM / 32)              // 64

__global__ __launch_bounds__(256, 2)
void gemm_f3(const __nv_bfloat16* __restrict__ Ahi,
             const __nv_bfloat16* __restrict__ Alo,
             const __nv_bfloat16* __restrict__ Bhi,
             const __nv_bfloat16* __restrict__ Blo,
             const float* __restrict__ bias,
             float* __restrict__ C, int Ntot) {
    extern __shared__ __nv_bfloat16 sm[];
    const uint32_t sbase = smem_u32(sm);

    const int tid  = threadIdx.x;
    const int lane = tid & 31;
    const int warp = tid >> 5;
    const int wm   = warp & 3;
    const int wn   = warp >> 2;
    const int bm   = blockIdx.y * 128;
    const int bn   = blockIdx.x * 128;

    const int lrow = tid >> 1;
    const int lc0  = (tid & 1) * 2;

    const int q2 = lane >> 3;
    const int lr = lane & 7;
    const int aMrow = wm * 32 + (q2 & 1) * 8 + lr;
    const int aKoff = (q2 >> 1) * 8;
    const int bNrow = wn * 64 + (q2 >> 1) * 8 + lr;
    const int bKoff = (q2 & 1) * 8;

    float acc[2][8][4];
#pragma unroll
    for (int i = 0; i < 2; i++)
#pragma unroll
        for (int j = 0; j < 8; j++)
#pragma unroll
            for (int r = 0; r < 4; r++) acc[i][j][r] = 0.0f;

    auto issue = [&](int it, int s) {
        const int kloc = it * 32;
        const uint32_t st = sbase + (uint32_t)s * FSTG;
        const size_t ga = (size_t)(bm + lrow) * KDIM + kloc;
        const size_t gb = (size_t)(bn + lrow) * KDIM + kloc;
#pragma unroll
        for (int j = 0; j < 2; j++) {
            const int c = lc0 + j;
            const uint32_t so = (uint32_t)(lrow * GSTR + c * 8) * 2;
            cp16(st + 0 * MSTG + so, Ahi + ga + c * 8);
            cp16(st + 1 * MSTG + so, Alo + ga + c * 8);
            cp16(st + 2 * MSTG + so, Bhi + gb + c * 8);
            cp16(st + 3 * MSTG + so, Blo + gb + c * 8);
        }
    };

    issue(0, 0);
    CP_COMMIT();

    for (int it = 0; it < FITERS; it++) {
        CP_WAIT(0);
        __syncthreads();
        if (it + 1 < FITERS) issue(it + 1, (it + 1) & 1);
        CP_COMMIT();

        const uint32_t st = sbase + (uint32_t)(it & 1) * FSTG;
#pragma unroll
        for (int q = 0; q < 2; q++) {
            uint32_t a0[2][4], a1[2][4];
#pragma unroll
            for (int mf = 0; mf < 2; mf++) {
                const uint32_t ao =
                    (uint32_t)(((aMrow + mf * 16) * GSTR + q * 16 + aKoff) * 2);
                ldm_x4(st + 0 * MSTG + ao, a0[mf][0], a0[mf][1], a0[mf][2], a0[mf][3]);
                ldm_x4(st + 1 * MSTG + ao, a1[mf][0], a1[mf][1], a1[mf][2], a1[mf][3]);
            }
            uint32_t bh[4][4], bl[4][4];
#pragma unroll
            for (int p = 0; p < 4; p++) {
                const uint32_t bo =
                    (uint32_t)(((bNrow + p * 16) * GSTR + q * 16 + bKoff) * 2);
                ldm_x4(st + 2 * MSTG + bo, bh[p][0], bh[p][1], bh[p][2], bh[p][3]);
                ldm_x4(st + 3 * MSTG + bo, bl[p][0], bl[p][1], bl[p][2], bl[p][3]);
            }
#pragma unroll
            for (int mf = 0; mf < 2; mf++)
#pragma unroll
                for (int nf = 0; nf < 8; nf++) {
                    const uint32_t h0 = bh[nf >> 1][(nf & 1) * 2 + 0];
                    const uint32_t h1 = bh[nf >> 1][(nf & 1) * 2 + 1];
                    mma16816(acc[mf][nf], a0[mf], h0, h1);
                    mma16816(acc[mf][nf], a1[mf], h0, h1);
                    mma16816(acc[mf][nf], a0[mf],
                             bl[nf >> 1][(nf & 1) * 2 + 0],
                             bl[nf >> 1][(nf & 1) * 2 + 1]);
                }
        }
    }

    const int mbase = bm + wm * 32 + (lane >> 2);
    const int nbase = bn + wn * 64 + (lane & 3) * 2;
#pragma unroll
    for (int mf = 0; mf < 2; mf++) {
#pragma unroll
        for (int nf = 0; nf < 8; nf++) {
            const int c = nbase + nf * 8;
            const float bi0 = __ldg(bias + c);
            const float bi1 = __ldg(bias + c + 1);
            const int r0 = mbase + mf * 16;
            *(float2*)(C + (size_t)r0 * Ntot + c) =
                make_float2(acc[mf][nf][0] + bi0, acc[mf][nf][1] + bi1);
            *(float2*)(C + (size_t)(r0 + 8) * Ntot + c) =
                make_float2(acc[mf][nf][2] + bi0, acc[mf][nf][3] + bi1);
        }
    }
}

// ---------------------------------------------------------------------------
// Highway combine + fused bf16 hi/lo split of new h
// ---------------------------------------------------------------------------
__global__ __launch_bounds__(256)
void highway_kernel(const float* __restrict__ p, float* __restrict__ h,
                    __nv_bfloat16* __restrict__ hhi,
                    __nv_bfloat16* __restrict__ hlo) {
    int idx = blockIdx.x * blockDim.x + threadIdx.x;
    int total = NTOK * (NFILT / 4);
    if (idx >= total) return;
    int m  = idx / (NFILT / 4);
    int j4 = idx % (NFILT / 4);

    const float4 pt = *(const float4*)(p + (size_t)m * (2 * NFILT) + j4 * 4);
    const float4 pg = *(const float4*)(p + (size_t)m * (2 * NFILT) + NFILT + j4 * 4);
    float4 hv = *(float4*)(h + (size_t)m * NFILT + j4 * 4);

    float g;
    g = 1.0f / (1.0f + expf(-pg.x)); hv.x = g * hv.x + (1.0f - g) * fmaxf(pt.x, 0.0f);
    g = 1.0f / (1.0f + expf(-pg.y)); hv.y = g * hv.y + (1.0f - g) * fmaxf(pt.y, 0.0f);
    g = 1.0f / (1.0f + expf(-pg.z)); hv.z = g * hv.z + (1.0f - g) * fmaxf(pt.z, 0.0f);
    g = 1.0f / (1.0f + expf(-pg.w)); hv.w = g * hv.w + (1.0f - g) * fmaxf(pt.w, 0.0f);

    *(float4*)(h + (size_t)m * NFILT + j4 * 4) = hv;

    __nv_bfloat16 h0 = __float2bfloat16(hv.x);
    __nv_bfloat16 h1 = __float2bfloat16(hv.y);
    __nv_bfloat16 h2 = __float2bfloat16(hv.z);
    __nv_bfloat16 h3 = __float2bfloat16(hv.w);
    __nv_bfloat162* hp = (__nv_bfloat162*)(hhi + (size_t)m * NFILT + j4 * 4);
    __nv_bfloat162* lp = (__nv_bfloat162*)(hlo + (size_t)m * NFILT + j4 * 4);
    hp[0] = __halves2bfloat162(h0, h1);
    hp[1] = __halves2bfloat162(h2, h3);
    lp[0] = __halves2bfloat162(__float2bfloat16(hv.x - __bfloat162float(h0)),
                               __float2bfloat16(hv.y - __bfloat162float(h1)));
    lp[1] = __halves2bfloat162(__float2bfloat16(hv.z - __bfloat162float(h2)),
                               __float2bfloat16(hv.w - __bfloat162float(h3)));
}

// ---------------------------------------------------------------------------
// Launch — weight splits forked onto side stream, hidden under conv.
//          my-index-3 (= ncu's profiled slot) is the first highway GEMM.
// ---------------------------------------------------------------------------
extern "C" void kernel_launch(void* const* d_in, const int* in_sizes, int n_in,
                              void* d_out, int out_size) {
    const int*   chars  = (const int*)d_in[1];
    const float* emb    = (const float*)d_in[2];
    const float* cw[7], *cb[7];
    for (int i = 0; i < 7; i++) {
        cw[i] = (const float*)d_in[3 + 2 * i];
        cb[i] = (const float*)d_in[4 + 2 * i];
    }
    const float* hw_w0  = (const float*)d_in[17];
    const float* hw_b0  = (const float*)d_in[18];
    const float* hw_w1  = (const float*)d_in[19];
    const float* hw_b1  = (const float*)d_in[20];
    const float* proj_w = (const float*)d_in[21];
    const float* proj_b = (const float*)d_in[22];
    float* out = (float*)d_out;

    static float *hbuf = nullptr, *pbuf = nullptr, *wtbuf = nullptr;
    static __nv_bfloat16 *hhi, *hlo, *w0hi, *w0lo, *w1hi, *w1lo, *wphi, *wplo;
    static cudaStream_t s2;
    static cudaEvent_t ev_fork, ev_w0, ev_w1, ev_wp;
    if (!hbuf) {
        cudaGetSymbolAddress((void**)&hbuf,  g_h);
        cudaGetSymbolAddress((void**)&pbuf,  g_p);
        cudaGetSymbolAddress((void**)&wtbuf, g_wt);
        cudaGetSymbolAddress((void**)&hhi,   g_hhi);
        cudaGetSymbolAddress((void**)&hlo,   g_hlo);
        cudaGetSymbolAddress((void**)&w0hi,  g_w0hi);
        cudaGetSymbolAddress((void**)&w0lo,  g_w0lo);
        cudaGetSymbolAddress((void**)&w1hi,  g_w1hi);
        cudaGetSymbolAddress((void**)&w1lo,  g_w1lo);
        cudaGetSymbolAddress((void**)&wphi,  g_wphi);
        cudaGetSymbolAddress((void**)&wplo,  g_wplo);
        cudaFuncSetAttribute(gemm_f3,
                             cudaFuncAttributeMaxDynamicSharedMemorySize,
                             F_DSMEM);
        cudaStreamCreateWithFlags(&s2, cudaStreamNonBlocking);
        cudaEventCreateWithFlags(&ev_fork, cudaEventDisableTiming);
        cudaEventCreateWithFlags(&ev_w0,   cudaEventDisableTiming);
        cudaEventCreateWithFlags(&ev_w1,   cudaEventDisableTiming);
        cudaEventCreateWithFlags(&ev_wp,   cudaEventDisableTiming);
    }

    dim3 blk(256);
    const int nW  = 2 * NFILT * NFILT;
    const int nWP = PROJ * NFILT;
    auto cvb = [](int n) { return (n / 4 + 255) / 256; };

    dim3 grid_hw(2 * NFILT / 128, NTOK / 128);   // (32, 32)
    dim3 grid_pr(PROJ / 128, NTOK / 128);        // (4, 32)
    int hw_blocks = (NTOK * (NFILT / 4) + 255) / 256;

    // launch 0 (main): merged conv-weight transpose
    transpose_all<<<(197120 + 255) / 256, blk>>>(cw[0], cw[1], cw[2], cw[3],
                                                 cw[4], cw[5], cw[6], wtbuf);
    // fork side stream off main
    cudaEventRecord(ev_fork, 0);
    cudaStreamWaitEvent(s2, ev_fork, 0);

    // launch 1 (s2): w0 split
    cvt_split<<<cvb(nW), blk, 0, s2>>>(hw_w0, w0hi, w0lo, nW / 4);
    cudaEventRecord(ev_w0, s2);

    // launch 2 (main): conv — runs concurrently with the splits on s2
    conv_kernel<<<NTOK, 256>>>(chars, emb, wtbuf,
                               cb[0], cb[1], cb[2], cb[3], cb[4], cb[5], cb[6],
                               hbuf, hhi, hlo);

    // launch 3 (main): highway-0 GEMM (ncu slot)
    cudaStreamWaitEvent(0, ev_w0, 0);
    gemm_f3<<<grid_hw, blk, F_DSMEM>>>(hhi, hlo, w0hi, w0lo, hw_b0,
                                       pbuf, 2 * NFILT);

    // launches 4-5 (s2): w1 + wp splits (run during conv/gemm0)
    cvt_split<<<cvb(nW), blk, 0, s2>>>(hw_w1, w1hi, w1lo, nW / 4);
    cudaEventRecord(ev_w1, s2);
    cvt_split<<<cvb(nWP), blk, 0, s2>>>(proj_w, wphi, wplo, nWP / 4);
    cudaEventRecord(ev_wp, s2);

    // launch 6 (main): highway-0 combine
    highway_kernel<<<hw_blocks, blk>>>(pbuf, hbuf, hhi, hlo);

    // launch 7 (main): highway-1 GEMM
    cudaStreamWaitEvent(0, ev_w1, 0);
    gemm_f3<<<grid_hw, blk, F_DSMEM>>>(hhi, hlo, w1hi, w1lo, hw_b1,
                                       pbuf, 2 * NFILT);
    // launch 8 (main): highway-1 combine
    highway_kernel<<<hw_blocks, blk>>>(pbuf, hbuf, hhi, hlo);

    // launch 9 (main): projection (joins s2 via ev_wp)
    cudaStreamWaitEvent(0, ev_wp, 0);
    gemm_f3<<<grid_pr, blk, F_DSMEM>>>(hhi, hlo, wphi, wplo, proj_b,
                                       out, PROJ);
}

// round 16
// speedup vs baseline: 1.2169x; 1.0147x over previous
#include <cuda_runtime.h>
#include <cuda_bf16.h>
#include <math.h>
#include <stdint.h>

// ---------------------------------------------------------------------------
// ConvTokenEmbedder: char CNN + highway x2 + projection
// Round 16: two-stream row-half pipelining — chain A (rows 0-2047) and
//           chain B (rows 2048-4095) overlap conv (FMA pipe) with GEMMs
//           (tensor pipe). Kernels = round-15 + row offsets.
// ---------------------------------------------------------------------------

#define NTOK   4096
#define NFILT  2048
#define PROJ   512
#define MAXC   50
#define CDIM   16
#define KDIM   2048
#define HALF   2048                    // rows per chain

typedef unsigned long long u64;

// Scratch
__device__ float g_h[NTOK * NFILT];
__device__ float g_p[NTOK * 2 * NFILT];
__device__ float g_wt[197120];
__device__ __nv_bfloat16 g_hhi[NTOK * NFILT];
__device__ __nv_bfloat16 g_hlo[NTOK * NFILT];
__device__ __nv_bfloat16 g_w0hi[2 * NFILT * NFILT];
__device__ __nv_bfloat16 g_w0lo[2 * NFILT * NFILT];
__device__ __nv_bfloat16 g_w1hi[2 * NFILT * NFILT];
__device__ __nv_bfloat16 g_w1lo[2 * NFILT * NFILT];
__device__ __nv_bfloat16 g_wphi[PROJ * NFILT];
__device__ __nv_bfloat16 g_wplo[PROJ * NFILT];

#define WT_O0 0
#define WT_O1 512
#define WT_O2 1536
#define WT_O3 4608
#define WT_O4 12800
#define WT_O5 33280
#define WT_O6 82432

// ---------------------------------------------------------------------------
// packed f32x2 helpers
// ---------------------------------------------------------------------------
__device__ __forceinline__ u64 fma_x2(u64 a, u64 b, u64 c) {
    u64 d;
    asm("fma.rn.f32x2 %0, %1, %2, %3;" : "=l"(d) : "l"(a), "l"(b), "l"(c));
    return d;
}
__device__ __forceinline__ u64 pack2(float lo, float hi) {
    u64 d;
    asm("mov.b64 %0, {%1, %2};" : "=l"(d) : "f"(lo), "f"(hi));
    return d;
}
__device__ __forceinline__ float2 unpack2(u64 v) {
    float lo, hi;
    asm("mov.b64 {%0, %1}, %2;" : "=f"(lo), "=f"(hi) : "l"(v));
    return make_float2(lo, hi);
}

// ---------------------------------------------------------------------------
// Merged weight transpose
// ---------------------------------------------------------------------------
__global__ __launch_bounds__(256)
void transpose_all(const float* __restrict__ w0, const float* __restrict__ w1,
                   const float* __restrict__ w2, const float* __restrict__ w3,
                   const float* __restrict__ w4, const float* __restrict__ w5,
                   const float* __restrict__ w6, float* __restrict__ out) {
    int idx = blockIdx.x * blockDim.x + threadIdx.x;
    if (idx >= 197120) return;
    const float* src;
    int base, nf, cw, local;
    if      (idx < 1536)  { if (idx < 512) { src = w0; base = WT_O0; nf = 32;  cw = 16; local = idx; }
                            else           { src = w1; base = WT_O1; nf = 32;  cw = 32; local = idx - 512; } }
    else if (idx < 4608)  { src = w2; base = WT_O2; nf = 64;   cw = 48;  local = idx - 1536; }
    else if (idx < 12800) { src = w3; base = WT_O3; nf = 128;  cw = 64;  local = idx - 4608; }
    else if (idx < 33280) { src = w4; base = WT_O4; nf = 256;  cw = 80;  local = idx - 12800; }
    else if (idx < 82432) { src = w5; base = WT_O5; nf = 512;  cw = 96;  local = idx - 33280; }
    else                  { src = w6; base = WT_O6; nf = 1024; cw = 112; local = idx - 82432; }
    int f = local / cw;
    int r = local - f * cw;
    out[base + r * nf + f] = src[local];
}

// ---------------------------------------------------------------------------
// Conv stage — packed two-chunk accumulation via fma.rn.f32x2
// ---------------------------------------------------------------------------
#define XS2_O1 0
#define XS2_O2 400
#define XS2_O3 816
#define XS2_O4 1232
#define XS2_O5 1664
#define XS2_O6 2096
#define XS2_O7 2544
#define XS2_TOT 2992

template <int W>
__device__ __forceinline__ float conv_max2(const u64* __restrict__ xs2,
                                           const float* __restrict__ wt,
                                           int nf, int f, float bias) {
    constexpr int NT = 51 - W;
    constexpr int TC = (NT + 1) / 2;
    constexpr int J  = TC + W - 1;
    u64 acc[TC];
#pragma unroll
    for (int t = 0; t < TC; t++) acc[t] = 0ULL;

#pragma unroll 2
    for (int c = 0; c < CDIM; c++) {
        u64 w2[W];
#pragma unroll
        for (int k = 0; k < W; k++) {
            float w = wt[(c * W + k) * nf + f];
            w2[k] = pack2(w, w);
        }
#pragma unroll
        for (int j = 0; j < J; j++) {
            u64 xv = xs2[c * J + j];
#pragma unroll
            for (int k = 0; k < W; k++) {
                int t = j - k;
                if (t >= 0 && t < TC) acc[t] = fma_x2(xv, w2[k], acc[t]);
            }
        }
    }
    float best = -3.4e38f;
#pragma unroll
    for (int t = 0; t < TC; t++) {
        float2 v = unpack2(acc[t]);
        best = fmaxf(best, fmaxf(v.x, v.y));
    }
    return fmaxf(best + bias, 0.0f);
}

__device__ __forceinline__ void store_split(float r, float* h,
                                            __nv_bfloat16* hi,
                                            __nv_bfloat16* lo, size_t o) {
    h[o] = r;
    __nv_bfloat16 hh = __float2bfloat16(r);
    hi[o] = hh;
    lo[o] = __float2bfloat16(r - __bfloat162float(hh));
}

__global__ __launch_bounds__(256)
void conv_kernel(const int*   __restrict__ chars,
                 const float* __restrict__ emb,
                 const float* __restrict__ wt,
                 const float* __restrict__ b0, const float* __restrict__ b1,
                 const float* __restrict__ b2, const float* __restrict__ b3,
                 const float* __restrict__ b4, const float* __restrict__ b5,
                 const float* __restrict__ b6,
                 float* __restrict__ h,
                 __nv_bfloat16* __restrict__ hhi,
                 __nv_bfloat16* __restrict__ hlo,
                 int noff) {
    __shared__ float xs[CDIM * 51];
    __shared__ int   chs[MAXC];
    __shared__ u64   xs2[XS2_TOT];

    const int n   = blockIdx.x + noff;
    const int tid = threadIdx.x;

    if (tid < MAXC) chs[tid] = chars[n * MAXC + tid];
    __syncthreads();
    for (int idx = tid; idx < MAXC * CDIM; idx += 256) {
        int t = idx >> 4;
        int c = idx & 15;
        xs[c * 51 + t] = emb[chs[t] * CDIM + c];
    }
    __syncthreads();

    {
        const int offs[7] = {XS2_O1, XS2_O2, XS2_O3, XS2_O4, XS2_O5, XS2_O6, XS2_O7};
        const int Js[7]   = {25, 26, 26, 27, 27, 28, 28};
        const int OFFs[7] = {25, 24, 24, 23, 23, 22, 22};
#pragma unroll
        for (int w = 0; w < 7; w++) {
            const int J = Js[w], OFF = OFFs[w];
            u64* dst = xs2 + offs[w];
            for (int idx = tid; idx < CDIM * J; idx += 256) {
                int c = idx / J;
                int j = idx - c * J;
                dst[idx] = pack2(xs[c * 51 + j], xs[c * 51 + OFF + j]);
            }
        }
    }
    __syncthreads();

    const size_t rowo = (size_t)n * NFILT;
    {
        int f = tid;
        float r;
        if (f < 32)        r = conv_max2<1>(xs2 + XS2_O1, wt + WT_O0, 32,  f,       b0[f]);
        else if (f < 64)   r = conv_max2<2>(xs2 + XS2_O2, wt + WT_O1, 32,  f - 32,  b1[f - 32]);
        else if (f < 128)  r = conv_max2<3>(xs2 + XS2_O3, wt + WT_O2, 64,  f - 64,  b2[f - 64]);
        else               r = conv_max2<4>(xs2 + XS2_O4, wt + WT_O3, 128, f - 128, b3[f - 128]);
        store_split(r, h, hhi, hlo, rowo + f);
    }
    {
        int f = tid;
        float r = conv_max2<5>(xs2 + XS2_O5, wt + WT_O4, 256, f, b4[f]);
        store_split(r, h, hhi, hlo, rowo + 256 + f);
    }
#pragma unroll
    for (int i = 0; i < 2; i++) {
        int f = tid + i * 256;
        float r = conv_max2<6>(xs2 + XS2_O6, wt + WT_O5, 512, f, b5[f]);
        store_split(r, h, hhi, hlo, rowo + 512 + f);
    }
#pragma unroll
    for (int i = 0; i < 4; i++) {
        int f = tid + i * 256;
        float r = conv_max2<7>(xs2 + XS2_O7, wt + WT_O6, 1024, f, b6[f]);
        store_split(r, h, hhi, hlo, rowo + 1024 + f);
    }
}

// ---------------------------------------------------------------------------
// fp32 -> (bf16 hi, bf16 lo) split (weights)
// ---------------------------------------------------------------------------
__global__ __launch_bounds__(256)
void cvt_split(const float* __restrict__ x,
               __nv_bfloat16* __restrict__ hi,
               __nv_bfloat16* __restrict__ lo, int n4) {
    int i = blockIdx.x * blockDim.x + threadIdx.x;
    if (i >= n4) return;
    float4 v = ((const float4*)x)[i];
    __nv_bfloat16 h0 = __float2bfloat16(v.x);
    __nv_bfloat16 h1 = __float2bfloat16(v.y);
    __nv_bfloat16 h2 = __float2bfloat16(v.z);
    __nv_bfloat16 h3 = __float2bfloat16(v.w);
    __nv_bfloat162* hp = (__nv_bfloat162*)hi + i * 2;
    __nv_bfloat162* lp = (__nv_bfloat162*)lo + i * 2;
    hp[0] = __halves2bfloat162(h0, h1);
    hp[1] = __halves2bfloat162(h2, h3);
    lp[0] = __halves2bfloat162(__float2bfloat16(v.x - __bfloat162float(h0)),
                               __float2bfloat16(v.y - __bfloat162float(h1)));
    lp[1] = __halves2bfloat162(__float2bfloat16(v.z - __bfloat162float(h2)),
                               __float2bfloat16(v.w - __bfloat162float(h3)));
}

// ---------------------------------------------------------------------------
// mma helpers
// ---------------------------------------------------------------------------
#define GSTR 40

__device__ __forceinline__ void ldm_x4(uint32_t addr, uint32_t& r0, uint32_t& r1,
                                       uint32_t& r2, uint32_t& r3) {
    asm volatile("ldmatrix.sync.aligned.m8n8.x4.shared.b16 {%0,%1,%2,%3}, [%4];"
                 : "=r"(r0), "=r"(r1), "=r"(r2), "=r"(r3) : "r"(addr));
}
__device__ __forceinline__ void mma16816(float* c, const uint32_t* a,
                                         uint32_t b0, uint32_t b1) {
    asm volatile(
        "mma.sync.aligned.m16n8k16.row.col.f32.bf16.bf16.f32 "
        "{%0,%1,%2,%3}, {%4,%5,%6,%7}, {%8,%9}, {%0,%1,%2,%3};"
        : "+f"(c[0]), "+f"(c[1]), "+f"(c[2]), "+f"(c[3])
        : "r"(a[0]), "r"(a[1]), "r"(a[2]), "r"(a[3]), "r"(b0), "r"(b1));
}
__device__ __forceinline__ void cp16(uint32_t s, const void* g) {
    asm volatile("cp.async.cg.shared.global [%0], [%1], 16;" :: "r"(s), "l"(g));
}
#define CP_COMMIT() asm volatile("cp.async.commit_group;" ::: "memory")
#define CP_WAIT(n)  asm volatile("cp.async.wait_group %0;" :: "n"(n) : "memory")

__device__ __forceinline__ uint32_t smem_u32(const void* p) {
    uint32_t a;
    asm("{ .reg .u64 t; cvta.to.shared.u64 t, %1; cvt.u32.u64 %0, t; }"
        : "=r"(a) : "l"(p));
    return a;
}

// ---------------------------------------------------------------------------
// Fused bf16x3 GEMM: CTA 128x128, 256 threads, warp 32x64, BK=32,
// 2 stages of {Ahi, Alo, Bhi, Blo} (round 14 verified). moff = M-tile offset.
// ---------------------------------------------------------------------------
#define MSTG  10240
#define FSTG  (4 * MSTG)
#define F_DSMEM (2 * FSTG)              // 81920
#define FITERS (KDIM / 32)              // 64

__global__ __launch_bounds__(256, 2)
void gemm_f3(const __nv_bfloat16* __restrict__ Ahi,
             const __nv_bfloat16* __restrict__ Alo,
             const __nv_bfloat16* __restrict__ Bhi,
             const __nv_bfloat16* __restrict__ Blo,
             const float* __restrict__ bias,
             float* __restrict__ C, int Ntot, int moff) {
    extern __shared__ __nv_bfloat16 sm[];
    const uint32_t sbase = smem_u32(sm);

    const int tid  = threadIdx.x;
    const int lane = tid & 31;
    const int warp = tid >> 5;
    const int wm   = warp & 3;
    const int wn   = warp >> 2;
    const int bm   = (blockIdx.y + moff) * 128;
    const int bn   = blockIdx.x * 128;

    const int lrow = tid >> 1;
    const int lc0  = (tid & 1) * 2;

    const int q2 = lane >> 3;
    const int lr = lane & 7;
    const int aMrow = wm * 32 + (q2 & 1) * 8 + lr;
    const int aKoff = (q2 >> 1) * 8;
    const int bNrow = wn * 64 + (q2 >> 1) * 8 + lr;
    const int bKoff = (q2 & 1) * 8;

    float acc[2][8][4];
#pragma unroll
    for (int i = 0; i < 2; i++)
#pragma unroll
        for (int j = 0; j < 8; j++)
#pragma unroll
            for (int r = 0; r < 4; r++) acc[i][j][r] = 0.0f;

    auto issue = [&](int it, int s) {
        const int kloc = it * 32;
        const uint32_t st = sbase + (uint32_t)s * FSTG;
        const size_t ga = (size_t)(bm + lrow) * KDIM + kloc;
        const size_t gb = (size_t)(bn + lrow) * KDIM + kloc;
#pragma unroll
        for (int j = 0; j < 2; j++) {
            const int c = lc0 + j;
            const uint32_t so = (uint32_t)(lrow * GSTR + c * 8) * 2;
            cp16(st + 0 * MSTG + so, Ahi + ga + c * 8);
            cp16(st + 1 * MSTG + so, Alo + ga + c * 8);
            cp16(st + 2 * MSTG + so, Bhi + gb + c * 8);
            cp16(st + 3 * MSTG + so, Blo + gb + c * 8);
        }
    };

    issue(0, 0);
    CP_COMMIT();

    for (int it = 0; it < FITERS; it++) {
        CP_WAIT(0);
        __syncthreads();
        if (it + 1 < FITERS) issue(it + 1, (it + 1) & 1);
        CP_COMMIT();

        const uint32_t st = sbase + (uint32_t)(it & 1) * FSTG;
#pragma unroll
        for (int q = 0; q < 2; q++) {
            uint32_t a0[2][4], a1[2][4];
#pragma unroll
            for (int mf = 0; mf < 2; mf++) {
                const uint32_t ao =
                    (uint32_t)(((aMrow + mf * 16) * GSTR + q * 16 + aKoff) * 2);
                ldm_x4(st + 0 * MSTG + ao, a0[mf][0], a0[mf][1], a0[mf][2], a0[mf][3]);
                ldm_x4(st + 1 * MSTG + ao, a1[mf][0], a1[mf][1], a1[mf][2], a1[mf][3]);
            }
            uint32_t b[4][4];
#pragma unroll
            for (int p = 0; p < 4; p++) {
                const uint32_t bo =
                    (uint32_t)(((bNrow + p * 16) * GSTR + q * 16 + bKoff) * 2);
                ldm_x4(st + 2 * MSTG + bo, b[p][0], b[p][1], b[p][2], b[p][3]);
            }
#pragma unroll
            for (int mf = 0; mf < 2; mf++)
#pragma unroll
                for (int nf = 0; nf < 8; nf++) {
                    const uint32_t bb0 = b[nf >> 1][(nf & 1) * 2 + 0];
                    const uint32_t bb1 = b[nf >> 1][(nf & 1) * 2 + 1];
                    mma16816(acc[mf][nf], a0[mf], bb0, bb1);
                    mma16816(acc[mf][nf], a1[mf], bb0, bb1);
                }
#pragma unroll
            for (int p = 0; p < 4; p++) {
                const uint32_t bo =
                    (uint32_t)(((bNrow + p * 16) * GSTR + q * 16 + bKoff) * 2);
                ldm_x4(st + 3 * MSTG + bo, b[p][0], b[p][1], b[p][2], b[p][3]);
            }
#pragma unroll
            for (int mf = 0; mf < 2; mf++)
#pragma unroll
                for (int nf = 0; nf < 8; nf++)
                    mma16816(acc[mf][nf], a0[mf],
                             b[nf >> 1][(nf & 1) * 2 + 0],
                             b[nf >> 1][(nf & 1) * 2 + 1]);
        }
    }

    const int mbase = bm + wm * 32 + (lane >> 2);
    const int nbase = bn + wn * 64 + (lane & 3) * 2;
#pragma unroll
    for (int mf = 0; mf < 2; mf++) {
#pragma unroll
        for (int nf = 0; nf < 8; nf++) {
            const int c = nbase + nf * 8;
            const float bi0 = __ldg(bias + c);
            const float bi1 = __ldg(bias + c + 1);
            const int r0 = mbase + mf * 16;
            *(float2*)(C + (size_t)r0 * Ntot + c) =
                make_float2(acc[mf][nf][0] + bi0, acc[mf][nf][1] + bi1);
            *(float2*)(C + (size_t)(r0 + 8) * Ntot + c) =
                make_float2(acc[mf][nf][2] + bi0, acc[mf][nf][3] + bi1);
        }
    }
}

// ---------------------------------------------------------------------------
// Highway combine + fused bf16 hi/lo split (pointers pre-offset by caller)
// ---------------------------------------------------------------------------
__global__ __launch_bounds__(256)
void highway_kernel(const float* __restrict__ p, float* __restrict__ h,
                    __nv_bfloat16* __restrict__ hhi,
                    __nv_bfloat16* __restrict__ hlo, int total) {
    int idx = blockIdx.x * blockDim.x + threadIdx.x;
    if (idx >= total) return;
    int m  = idx / (NFILT / 4);
    int j4 = idx % (NFILT / 4);

    const float4 pt = *(const float4*)(p + (size_t)m * (2 * NFILT) + j4 * 4);
    const float4 pg = *(const float4*)(p + (size_t)m * (2 * NFILT) + NFILT + j4 * 4);
    float4 hv = *(float4*)(h + (size_t)m * NFILT + j4 * 4);

    float g;
    g = 1.0f / (1.0f + expf(-pg.x)); hv.x = g * hv.x + (1.0f - g) * fmaxf(pt.x, 0.0f);
    g = 1.0f / (1.0f + expf(-pg.y)); hv.y = g * hv.y + (1.0f - g) * fmaxf(pt.y, 0.0f);
    g = 1.0f / (1.0f + expf(-pg.z)); hv.z = g * hv.z + (1.0f - g) * fmaxf(pt.z, 0.0f);
    g = 1.0f / (1.0f + expf(-pg.w)); hv.w = g * hv.w + (1.0f - g) * fmaxf(pt.w, 0.0f);

    *(float4*)(h + (size_t)m * NFILT + j4 * 4) = hv;

    __nv_bfloat16 h0 = __float2bfloat16(hv.x);
    __nv_bfloat16 h1 = __float2bfloat16(hv.y);
    __nv_bfloat16 h2 = __float2bfloat16(hv.z);
    __nv_bfloat16 h3 = __float2bfloat16(hv.w);
    __nv_bfloat162* hp = (__nv_bfloat162*)(hhi + (size_t)m * NFILT + j4 * 4);
    __nv_bfloat162* lp = (__nv_bfloat162*)(hlo + (size_t)m * NFILT + j4 * 4);
    hp[0] = __halves2bfloat162(h0, h1);
    hp[1] = __halves2bfloat162(h2, h3);
    lp[0] = __halves2bfloat162(__float2bfloat16(hv.x - __bfloat162float(h0)),
                               __float2bfloat16(hv.y - __bfloat162float(h1)));
    lp[1] = __halves2bfloat162(__float2bfloat16(hv.z - __bfloat162float(h2)),
                               __float2bfloat16(hv.w - __bfloat162float(h3)));
}

// ---------------------------------------------------------------------------
// Launch — two row-half chains on two streams
// ---------------------------------------------------------------------------
extern "C" void kernel_launch(void* const* d_in, const int* in_sizes, int n_in,
                              void* d_out, int out_size) {
    const int*   chars  = (const int*)d_in[1];
    const float* emb    = (const float*)d_in[2];
    const float* cw[7], *cb[7];
    for (int i = 0; i < 7; i++) {
        cw[i] = (const float*)d_in[3 + 2 * i];
        cb[i] = (const float*)d_in[4 + 2 * i];
    }
    const float* hw_w0  = (const float*)d_in[17];
    const float* hw_b0  = (const float*)d_in[18];
    const float* hw_w1  = (const float*)d_in[19];
    const float* hw_b1  = (const float*)d_in[20];
    const float* proj_w = (const float*)d_in[21];
    const float* proj_b = (const float*)d_in[22];
    float* out = (float*)d_out;

    static float *hbuf = nullptr, *pbuf = nullptr, *wtbuf = nullptr;
    static __nv_bfloat16 *hhi, *hlo, *w0hi, *w0lo, *w1hi, *w1lo, *wphi, *wplo;
    static cudaStream_t s2;
    static cudaEvent_t ev_fork, ev_w0, ev_w1, ev_wp, ev_done;
    if (!hbuf) {
        cudaGetSymbolAddress((void**)&hbuf,  g_h);
        cudaGetSymbolAddress((void**)&pbuf,  g_p);
        cudaGetSymbolAddress((void**)&wtbuf, g_wt);
        cudaGetSymbolAddress((void**)&hhi,   g_hhi);
        cudaGetSymbolAddress((void**)&hlo,   g_hlo);
        cudaGetSymbolAddress((void**)&w0hi,  g_w0hi);
        cudaGetSymbolAddress((void**)&w0lo,  g_w0lo);
        cudaGetSymbolAddress((void**)&w1hi,  g_w1hi);
        cudaGetSymbolAddress((void**)&w1lo,  g_w1lo);
        cudaGetSymbolAddress((void**)&wphi,  g_wphi);
        cudaGetSymbolAddress((void**)&wplo,  g_wplo);
        cudaFuncSetAttribute(gemm_f3,
                             cudaFuncAttributeMaxDynamicSharedMemorySize,
                             F_DSMEM);
        cudaStreamCreateWithFlags(&s2, cudaStreamNonBlocking);
        cudaEventCreateWithFlags(&ev_fork, cudaEventDisableTiming);
        cudaEventCreateWithFlags(&ev_w0,   cudaEventDisableTiming);
        cudaEventCreateWithFlags(&ev_w1,   cudaEventDisableTiming);
        cudaEventCreateWithFlags(&ev_wp,   cudaEventDisableTiming);
        cudaEventCreateWithFlags(&ev_done, cudaEventDisableTiming);
    }

    dim3 blk(256);
    const int nW  = 2 * NFILT * NFILT;
    const int nWP = PROJ * NFILT;
    auto cvb = [](int n) { return (n / 4 + 255) / 256; };

    dim3 grid_hwH(2 * NFILT / 128, HALF / 128);  // (32, 16) per half
    dim3 grid_prH(PROJ / 128, HALF / 128);       // (4, 16) per half
    const int hwTotH   = HALF * (NFILT / 4);
    const int hwBlocksH = (hwTotH + 255) / 256;

    // B-chain pointer offsets (rows 2048..4095)
    const size_t hOffB = (size_t)HALF * NFILT;
    const size_t pOffB = (size_t)HALF * 2 * NFILT;

    // --- main: transpose, then fork ---
    transpose_all<<<(197120 + 255) / 256, blk>>>(cw[0], cw[1], cw[2], cw[3],
                                                 cw[4], cw[5], cw[6], wtbuf);
    cudaEventRecord(ev_fork, 0);
    cudaStreamWaitEvent(s2, ev_fork, 0);

    // --- s2: weight splits first (needed by both chains) ---
    cvt_split<<<cvb(nW), blk, 0, s2>>>(hw_w0, w0hi, w0lo, nW / 4);
    cudaEventRecord(ev_w0, s2);
    cvt_split<<<cvb(nW), blk, 0, s2>>>(hw_w1, w1hi, w1lo, nW / 4);
    cudaEventRecord(ev_w1, s2);
    cvt_split<<<cvb(nWP), blk, 0, s2>>>(proj_w, wphi, wplo, nWP / 4);
    cudaEventRecord(ev_wp, s2);

    // --- main: chain A (rows 0..2047) ---
    conv_kernel<<<HALF, 256>>>(chars, emb, wtbuf,
                               cb[0], cb[1], cb[2], cb[3], cb[4], cb[5], cb[6],
                               hbuf, hhi, hlo, 0);
    cudaStreamWaitEvent(0, ev_w0, 0);
    gemm_f3<<<grid_hwH, blk, F_DSMEM>>>(hhi, hlo, w0hi, w0lo, hw_b0,
                                        pbuf, 2 * NFILT, 0);
    highway_kernel<<<hwBlocksH, blk>>>(pbuf, hbuf, hhi, hlo, hwTotH);
    cudaStreamWaitEvent(0, ev_w1, 0);
    gemm_f3<<<grid_hwH, blk, F_DSMEM>>>(hhi, hlo, w1hi, w1lo, hw_b1,
                                        pbuf, 2 * NFILT, 0);
    highway_kernel<<<hwBlocksH, blk>>>(pbuf, hbuf, hhi, hlo, hwTotH);
    cudaStreamWaitEvent(0, ev_wp, 0);
    gemm_f3<<<grid_prH, blk, F_DSMEM>>>(hhi, hlo, wphi, wplo, proj_b,
                                        out, PROJ, 0);

    // --- s2: chain B (rows 2048..4095) ---
    conv_kernel<<<HALF, 256, 0, s2>>>(chars, emb, wtbuf,
                                      cb[0], cb[1], cb[2], cb[3], cb[4], cb[5],
                                      cb[6], hbuf, hhi, hlo, HALF);
    gemm_f3<<<grid_hwH, blk, F_DSMEM, s2>>>(hhi, hlo, w0hi, w0lo, hw_b0,
                                            pbuf, 2 * NFILT, HALF / 128);
    highway_kernel<<<hwBlocksH, blk, 0, s2>>>(pbuf + pOffB, hbuf + hOffB,
                                              hhi + hOffB, hlo + hOffB, hwTotH);
    gemm_f3<<<grid_hwH, blk, F_DSMEM, s2>>>(hhi, hlo, w1hi, w1lo, hw_b1,
                                            pbuf, 2 * NFILT, HALF / 128);
    highway_kernel<<<hwBlocksH, blk, 0, s2>>>(pbuf + pOffB, hbuf + hOffB,
                                              hhi + hOffB, hlo + hOffB, hwTotH);
    gemm_f3<<<grid_prH, blk, F_DSMEM, s2>>>(hhi, hlo, wphi, wplo, proj_b,
                                            out, PROJ, HALF / 128);

    // --- join B back to main ---
    cudaEventRecord(ev_done, s2);
    cudaStreamWaitEvent(0, ev_done, 0);
}

// round 17
// speedup vs baseline: 1.2327x; 1.0129x over previous
#include <cuda_runtime.h>
#include <cuda_bf16.h>
#include <math.h>
#include <stdint.h>

// ---------------------------------------------------------------------------
// ConvTokenEmbedder: char CNN + highway x2 + projection
// Round 17: gemm_f3 -> 128x64 tile, 32x32 warp tiles, 3 CTAs/SM (3 barrier
//           domains, 24 warps/SM). conv moved to ncu slot 3 for evidence.
//           Two-stream halves kept from round 16.
// ---------------------------------------------------------------------------

#define NTOK   4096
#define NFILT  2048
#define PROJ   512
#define MAXC   50
#define CDIM   16
#define KDIM   2048
#define HALF   2048

typedef unsigned long long u64;

// Scratch
__device__ float g_h[NTOK * NFILT];
__device__ float g_p[NTOK * 2 * NFILT];
__device__ float g_wt[197120];
__device__ __nv_bfloat16 g_hhi[NTOK * NFILT];
__device__ __nv_bfloat16 g_hlo[NTOK * NFILT];
__device__ __nv_bfloat16 g_w0hi[2 * NFILT * NFILT];
__device__ __nv_bfloat16 g_w0lo[2 * NFILT * NFILT];
__device__ __nv_bfloat16 g_w1hi[2 * NFILT * NFILT];
__device__ __nv_bfloat16 g_w1lo[2 * NFILT * NFILT];
__device__ __nv_bfloat16 g_wphi[PROJ * NFILT];
__device__ __nv_bfloat16 g_wplo[PROJ * NFILT];

#define WT_O0 0
#define WT_O1 512
#define WT_O2 1536
#define WT_O3 4608
#define WT_O4 12800
#define WT_O5 33280
#define WT_O6 82432

// ---------------------------------------------------------------------------
// packed f32x2 helpers
// ---------------------------------------------------------------------------
__device__ __forceinline__ u64 fma_x2(u64 a, u64 b, u64 c) {
    u64 d;
    asm("fma.rn.f32x2 %0, %1, %2, %3;" : "=l"(d) : "l"(a), "l"(b), "l"(c));
    return d;
}
__device__ __forceinline__ u64 pack2(float lo, float hi) {
    u64 d;
    asm("mov.b64 %0, {%1, %2};" : "=l"(d) : "f"(lo), "f"(hi));
    return d;
}
__device__ __forceinline__ float2 unpack2(u64 v) {
    float lo, hi;
    asm("mov.b64 {%0, %1}, %2;" : "=f"(lo), "=f"(hi) : "l"(v));
    return make_float2(lo, hi);
}

// ---------------------------------------------------------------------------
// Merged weight transpose
// ---------------------------------------------------------------------------
__global__ __launch_bounds__(256)
void transpose_all(const float* __restrict__ w0, const float* __restrict__ w1,
                   const float* __restrict__ w2, const float* __restrict__ w3,
                   const float* __restrict__ w4, const float* __restrict__ w5,
                   const float* __restrict__ w6, float* __restrict__ out) {
    int idx = blockIdx.x * blockDim.x + threadIdx.x;
    if (idx >= 197120) return;
    const float* src;
    int base, nf, cw, local;
    if      (idx < 1536)  { if (idx < 512) { src = w0; base = WT_O0; nf = 32;  cw = 16; local = idx; }
                            else           { src = w1; base = WT_O1; nf = 32;  cw = 32; local = idx - 512; } }
    else if (idx < 4608)  { src = w2; base = WT_O2; nf = 64;   cw = 48;  local = idx - 1536; }
    else if (idx < 12800) { src = w3; base = WT_O3; nf = 128;  cw = 64;  local = idx - 4608; }
    else if (idx < 33280) { src = w4; base = WT_O4; nf = 256;  cw = 80;  local = idx - 12800; }
    else if (idx < 82432) { src = w5; base = WT_O5; nf = 512;  cw = 96;  local = idx - 33280; }
    else                  { src = w6; base = WT_O6; nf = 1024; cw = 112; local = idx - 82432; }
    int f = local / cw;
    int r = local - f * cw;
    out[base + r * nf + f] = src[local];
}

// ---------------------------------------------------------------------------
// Conv stage — packed two-chunk accumulation via fma.rn.f32x2
// ---------------------------------------------------------------------------
#define XS2_O1 0
#define XS2_O2 400
#define XS2_O3 816
#define XS2_O4 1232
#define XS2_O5 1664
#define XS2_O6 2096
#define XS2_O7 2544
#define XS2_TOT 2992

template <int W>
__device__ __forceinline__ float conv_max2(const u64* __restrict__ xs2,
                                           const float* __restrict__ wt,
                                           int nf, int f, float bias) {
    constexpr int NT = 51 - W;
    constexpr int TC = (NT + 1) / 2;
    constexpr int J  = TC + W - 1;
    u64 acc[TC];
#pragma unroll
    for (int t = 0; t < TC; t++) acc[t] = 0ULL;

#pragma unroll 2
    for (int c = 0; c < CDIM; c++) {
        u64 w2[W];
#pragma unroll
        for (int k = 0; k < W; k++) {
            float w = wt[(c * W + k) * nf + f];
            w2[k] = pack2(w, w);
        }
#pragma unroll
        for (int j = 0; j < J; j++) {
            u64 xv = xs2[c * J + j];
#pragma unroll
            for (int k = 0; k < W; k++) {
                int t = j - k;
                if (t >= 0 && t < TC) acc[t] = fma_x2(xv, w2[k], acc[t]);
            }
        }
    }
    float best = -3.4e38f;
#pragma unroll
    for (int t = 0; t < TC; t++) {
        float2 v = unpack2(acc[t]);
        best = fmaxf(best, fmaxf(v.x, v.y));
    }
    return fmaxf(best + bias, 0.0f);
}

__device__ __forceinline__ void store_split(float r, float* h,
                                            __nv_bfloat16* hi,
                                            __nv_bfloat16* lo, size_t o) {
    h[o] = r;
    __nv_bfloat16 hh = __float2bfloat16(r);
    hi[o] = hh;
    lo[o] = __float2bfloat16(r - __bfloat162float(hh));
}

__global__ __launch_bounds__(256)
void conv_kernel(const int*   __restrict__ chars,
                 const float* __restrict__ emb,
                 const float* __restrict__ wt,
                 const float* __restrict__ b0, const float* __restrict__ b1,
                 const float* __restrict__ b2, const float* __restrict__ b3,
                 const float* __restrict__ b4, const float* __restrict__ b5,
                 const float* __restrict__ b6,
                 float* __restrict__ h,
                 __nv_bfloat16* __restrict__ hhi,
                 __nv_bfloat16* __restrict__ hlo,
                 int noff) {
    __shared__ float xs[CDIM * 51];
    __shared__ int   chs[MAXC];
    __shared__ u64   xs2[XS2_TOT];

    const int n   = blockIdx.x + noff;
    const int tid = threadIdx.x;

    if (tid < MAXC) chs[tid] = chars[n * MAXC + tid];
    __syncthreads();
    for (int idx = tid; idx < MAXC * CDIM; idx += 256) {
        int t = idx >> 4;
        int c = idx & 15;
        xs[c * 51 + t] = emb[chs[t] * CDIM + c];
    }
    __syncthreads();

    {
        const int offs[7] = {XS2_O1, XS2_O2, XS2_O3, XS2_O4, XS2_O5, XS2_O6, XS2_O7};
        const int Js[7]   = {25, 26, 26, 27, 27, 28, 28};
        const int OFFs[7] = {25, 24, 24, 23, 23, 22, 22};
#pragma unroll
        for (int w = 0; w < 7; w++) {
            const int J = Js[w], OFF = OFFs[w];
            u64* dst = xs2 + offs[w];
            for (int idx = tid; idx < CDIM * J; idx += 256) {
                int c = idx / J;
                int j = idx - c * J;
                dst[idx] = pack2(xs[c * 51 + j], xs[c * 51 + OFF + j]);
            }
        }
    }
    __syncthreads();

    const size_t rowo = (size_t)n * NFILT;
    {
        int f = tid;
        float r;
        if (f < 32)        r = conv_max2<1>(xs2 + XS2_O1, wt + WT_O0, 32,  f,       b0[f]);
        else if (f < 64)   r = conv_max2<2>(xs2 + XS2_O2, wt + WT_O1, 32,  f - 32,  b1[f - 32]);
        else if (f < 128)  r = conv_max2<3>(xs2 + XS2_O3, wt + WT_O2, 64,  f - 64,  b2[f - 64]);
        else               r = conv_max2<4>(xs2 + XS2_O4, wt + WT_O3, 128, f - 128, b3[f - 128]);
        store_split(r, h, hhi, hlo, rowo + f);
    }
    {
        int f = tid;
        float r = conv_max2<5>(xs2 + XS2_O5, wt + WT_O4, 256, f, b4[f]);
        store_split(r, h, hhi, hlo, rowo + 256 + f);
    }
#pragma unroll
    for (int i = 0; i < 2; i++) {
        int f = tid + i * 256;
        float r = conv_max2<6>(xs2 + XS2_O6, wt + WT_O5, 512, f, b5[f]);
        store_split(r, h, hhi, hlo, rowo + 512 + f);
    }
#pragma unroll
    for (int i = 0; i < 4; i++) {
        int f = tid + i * 256;
        float r = conv_max2<7>(xs2 + XS2_O7, wt + WT_O6, 1024, f, b6[f]);
        store_split(r, h, hhi, hlo, rowo + 1024 + f);
    }
}

// ---------------------------------------------------------------------------
// fp32 -> (bf16 hi, bf16 lo) split (weights)
// ---------------------------------------------------------------------------
__global__ __launch_bounds__(256)
void cvt_split(const float* __restrict__ x,
               __nv_bfloat16* __restrict__ hi,
               __nv_bfloat16* __restrict__ lo, int n4) {
    int i = blockIdx.x * blockDim.x + threadIdx.x;
    if (i >= n4) return;
    float4 v = ((const float4*)x)[i];
    __nv_bfloat16 h0 = __float2bfloat16(v.x);
    __nv_bfloat16 h1 = __float2bfloat16(v.y);
    __nv_bfloat16 h2 = __float2bfloat16(v.z);
    __nv_bfloat16 h3 = __float2bfloat16(v.w);
    __nv_bfloat162* hp = (__nv_bfloat162*)hi + i * 2;
    __nv_bfloat162* lp = (__nv_bfloat162*)lo + i * 2;
    hp[0] = __halves2bfloat162(h0, h1);
    hp[1] = __halves2bfloat162(h2, h3);
    lp[0] = __halves2bfloat162(__float2bfloat16(v.x - __bfloat162float(h0)),
                               __float2bfloat16(v.y - __bfloat162float(h1)));
    lp[1] = __halves2bfloat162(__float2bfloat16(v.z - __bfloat162float(h2)),
                               __float2bfloat16(v.w - __bfloat162float(h3)));
}

// ---------------------------------------------------------------------------
// mma helpers
// ---------------------------------------------------------------------------
#define GSTR 40

__device__ __forceinline__ void ldm_x4(uint32_t addr, uint32_t& r0, uint32_t& r1,
                                       uint32_t& r2, uint32_t& r3) {
    asm volatile("ldmatrix.sync.aligned.m8n8.x4.shared.b16 {%0,%1,%2,%3}, [%4];"
                 : "=r"(r0), "=r"(r1), "=r"(r2), "=r"(r3) : "r"(addr));
}
__device__ __forceinline__ void mma16816(float* c, const uint32_t* a,
                                         uint32_t b0, uint32_t b1) {
    asm volatile(
        "mma.sync.aligned.m16n8k16.row.col.f32.bf16.bf16.f32 "
        "{%0,%1,%2,%3}, {%4,%5,%6,%7}, {%8,%9}, {%0,%1,%2,%3};"
        : "+f"(c[0]), "+f"(c[1]), "+f"(c[2]), "+f"(c[3])
        : "r"(a[0]), "r"(a[1]), "r"(a[2]), "r"(a[3]), "r"(b0), "r"(b1));
}
__device__ __forceinline__ void cp16(uint32_t s, const void* g) {
    asm volatile("cp.async.cg.shared.global [%0], [%1], 16;" :: "r"(s), "l"(g));
}
#define CP_COMMIT() asm volatile("cp.async.commit_group;" ::: "memory")
#define CP_WAIT(n)  asm volatile("cp.async.wait_group %0;" :: "n"(n) : "memory")

__device__ __forceinline__ uint32_t smem_u32(const void* p) {
    uint32_t a;
    asm("{ .reg .u64 t; cvta.to.shared.u64 t, %1; cvt.u32.u64 %0, t; }"
        : "=r"(a) : "l"(p));
    return a;
}

// ---------------------------------------------------------------------------
// Fused bf16x3 GEMM: CTA 128x64, 256 threads, warp 32x32, BK=32,
// 2 stages of {Ahi, Alo, Bhi, Blo}, 3 CTAs/SM (24 warps, 3 barrier domains).
// ---------------------------------------------------------------------------
#define A_MSTG 10240                    // 128*GSTR*2
#define B_MSTG 5120                     // 64*GSTR*2
#define FSTG   (2 * A_MSTG + 2 * B_MSTG)   // 30720
#define F_DSMEM (2 * FSTG)              // 61440
#define FITERS (KDIM / 32)              // 64
// stage-internal offsets
#define OFF_AHI 0
#define OFF_ALO A_MSTG
#define OFF_BHI (2 * A_MSTG)
#define OFF_BLO (2 * A_MSTG + B_MSTG)

__global__ __launch_bounds__(256, 3)
void gemm_f3(const __nv_bfloat16* __restrict__ Ahi,
             const __nv_bfloat16* __restrict__ Alo,
             const __nv_bfloat16* __restrict__ Bhi,
             const __nv_bfloat16* __restrict__ Blo,
             const float* __restrict__ bias,
             float* __restrict__ C, int Ntot, int moff) {
    extern __shared__ __nv_bfloat16 sm[];
    const uint32_t sbase = smem_u32(sm);

    const int tid  = threadIdx.x;
    const int lane = tid & 31;
    const int warp = tid >> 5;
    const int wm   = warp & 3;          // 4 m-warps of 32 rows
    const int wn   = warp >> 2;         // 2 n-warps of 32 cols
    const int bm   = (blockIdx.y + moff) * 128;
    const int bn   = blockIdx.x * 64;

    const int lrowA = tid >> 1;         // 0..127 (A rows)
    const int lc0A  = (tid & 1) * 2;    // A chunk pair
    const int lrowB = tid >> 2;         // 0..63 (B rows)
    const int lcB   = tid & 3;          // B chunk

    const int q2 = lane >> 3;
    const int lr = lane & 7;
    const int aMrow = wm * 32 + (q2 & 1) * 8 + lr;
    const int aKoff = (q2 >> 1) * 8;
    const int bNrow = wn * 32 + (q2 >> 1) * 8 + lr;
    const int bKoff = (q2 & 1) * 8;

    float acc[2][4][4];
#pragma unroll
    for (int i = 0; i < 2; i++)
#pragma unroll
        for (int j = 0; j < 4; j++)
#pragma unroll
            for (int r = 0; r < 4; r++) acc[i][j][r] = 0.0f;

    auto issue = [&](int it, int s) {
        const int kloc = it * 32;
        const uint32_t st = sbase + (uint32_t)s * FSTG;
        const size_t ga = (size_t)(bm + lrowA) * KDIM + kloc;
        const size_t gb = (size_t)(bn + lrowB) * KDIM + kloc;
#pragma unroll
        for (int j = 0; j < 2; j++) {
            const int c = lc0A + j;
            const uint32_t so = (uint32_t)(lrowA * GSTR + c * 8) * 2;
            cp16(st + OFF_AHI + so, Ahi + ga + c * 8);
            cp16(st + OFF_ALO + so, Alo + ga + c * 8);
        }
        {
            const uint32_t so = (uint32_t)(lrowB * GSTR + lcB * 8) * 2;
            cp16(st + OFF_BHI + so, Bhi + gb + lcB * 8);
            cp16(st + OFF_BLO + so, Blo + gb + lcB * 8);
        }
    };

    issue(0, 0);
    CP_COMMIT();

    for (int it = 0; it < FITERS; it++) {
        CP_WAIT(0);
        __syncthreads();
        if (it + 1 < FITERS) issue(it + 1, (it + 1) & 1);
        CP_COMMIT();

        const uint32_t st = sbase + (uint32_t)(it & 1) * FSTG;
#pragma unroll
        for (int q = 0; q < 2; q++) {
            uint32_t a0[2][4], a1[2][4];
#pragma unroll
            for (int mf = 0; mf < 2; mf++) {
                const uint32_t ao =
                    (uint32_t)(((aMrow + mf * 16) * GSTR + q * 16 + aKoff) * 2);
                ldm_x4(st + OFF_AHI + ao, a0[mf][0], a0[mf][1], a0[mf][2], a0[mf][3]);
                ldm_x4(st + OFF_ALO + ao, a1[mf][0], a1[mf][1], a1[mf][2], a1[mf][3]);
            }
            uint32_t b[2][4];
            // Bhi: hi*hi and lo*hi
#pragma unroll
            for (int p = 0; p < 2; p++) {
                const uint32_t bo =
                    (uint32_t)(((bNrow + p * 16) * GSTR + q * 16 + bKoff) * 2);
                ldm_x4(st + OFF_BHI + bo, b[p][0], b[p][1], b[p][2], b[p][3]);
            }
#pragma unroll
            for (int mf = 0; mf < 2; mf++)
#pragma unroll
                for (int nf = 0; nf < 4; nf++) {
                    const uint32_t bb0 = b[nf >> 1][(nf & 1) * 2 + 0];
                    const uint32_t bb1 = b[nf >> 1][(nf & 1) * 2 + 1];
                    mma16816(acc[mf][nf], a0[mf], bb0, bb1);
                    mma16816(acc[mf][nf], a1[mf], bb0, bb1);
                }
            // Blo: hi*lo
#pragma unroll
            for (int p = 0; p < 2; p++) {
                const uint32_t bo =
                    (uint32_t)(((bNrow + p * 16) * GSTR + q * 16 + bKoff) * 2);
                ldm_x4(st + OFF_BLO + bo, b[p][0], b[p][1], b[p][2], b[p][3]);
            }
#pragma unroll
            for (int mf = 0; mf < 2; mf++)
#pragma unroll
                for (int nf = 0; nf < 4; nf++)
                    mma16816(acc[mf][nf], a0[mf],
                             b[nf >> 1][(nf & 1) * 2 + 0],
                             b[nf >> 1][(nf & 1) * 2 + 1]);
        }
    }

    const int mbase = bm + wm * 32 + (lane >> 2);
    const int nbase = bn + wn * 32 + (lane & 3) * 2;
#pragma unroll
    for (int mf = 0; mf < 2; mf++) {
#pragma unroll
        for (int nf = 0; nf < 4; nf++) {
            const int c = nbase + nf * 8;
            const float bi0 = __ldg(bias + c);
            const float bi1 = __ldg(bias + c + 1);
            const int r0 = mbase + mf * 16;
            *(float2*)(C + (size_t)r0 * Ntot + c) =
                make_float2(acc[mf][nf][0] + bi0, acc[mf][nf][1] + bi1);
            *(float2*)(C + (size_t)(r0 + 8) * Ntot + c) =
                make_float2(acc[mf][nf][2] + bi0, acc[mf][nf][3] + bi1);
        }
    }
}

// ---------------------------------------------------------------------------
// Highway combine + fused bf16 hi/lo split (pointers pre-offset by caller)
// ---------------------------------------------------------------------------
__global__ __launch_bounds__(256)
void highway_kernel(const float* __restrict__ p, float* __restrict__ h,
                    __nv_bfloat16* __restrict__ hhi,
                    __nv_bfloat16* __restrict__ hlo, int total) {
    int idx = blockIdx.x * blockDim.x + threadIdx.x;
    if (idx >= total) return;
    int m  = idx / (NFILT / 4);
    int j4 = idx % (NFILT / 4);

    const float4 pt = *(const float4*)(p + (size_t)m * (2 * NFILT) + j4 * 4);
    const float4 pg = *(const float4*)(p + (size_t)m * (2 * NFILT) + NFILT + j4 * 4);
    float4 hv = *(float4*)(h + (size_t)m * NFILT + j4 * 4);

    float g;
    g = 1.0f / (1.0f + expf(-pg.x)); hv.x = g * hv.x + (1.0f - g) * fmaxf(pt.x, 0.0f);
    g = 1.0f / (1.0f + expf(-pg.y)); hv.y = g * hv.y + (1.0f - g) * fmaxf(pt.y, 0.0f);
    g = 1.0f / (1.0f + expf(-pg.z)); hv.z = g * hv.z + (1.0f - g) * fmaxf(pt.z, 0.0f);
    g = 1.0f / (1.0f + expf(-pg.w)); hv.w = g * hv.w + (1.0f - g) * fmaxf(pt.w, 0.0f);

    *(float4*)(h + (size_t)m * NFILT + j4 * 4) = hv;

    __nv_bfloat16 h0 = __float2bfloat16(hv.x);
    __nv_bfloat16 h1 = __float2bfloat16(hv.y);
    __nv_bfloat16 h2 = __float2bfloat16(hv.z);
    __nv_bfloat16 h3 = __float2bfloat16(hv.w);
    __nv_bfloat162* hp = (__nv_bfloat162*)(hhi + (size_t)m * NFILT + j4 * 4);
    __nv_bfloat162* lp = (__nv_bfloat162*)(hlo + (size_t)m * NFILT + j4 * 4);
    hp[0] = __halves2bfloat162(h0, h1);
    hp[1] = __halves2bfloat162(h2, h3);
    lp[0] = __halves2bfloat162(__float2bfloat16(hv.x - __bfloat162float(h0)),
                               __float2bfloat16(hv.y - __bfloat162float(h1)));
    lp[1] = __halves2bfloat162(__float2bfloat16(hv.z - __bfloat162float(h2)),
                               __float2bfloat16(hv.w - __bfloat162float(h3)));
}

// ---------------------------------------------------------------------------
// Launch — two row-half chains; conv_A at enqueue index 3 (ncu slot)
// ---------------------------------------------------------------------------
extern "C" void kernel_launch(void* const* d_in, const int* in_sizes, int n_in,
                              void* d_out, int out_size) {
    const int*   chars  = (const int*)d_in[1];
    const float* emb    = (const float*)d_in[2];
    const float* cw[7], *cb[7];
    for (int i = 0; i < 7; i++) {
        cw[i] = (const float*)d_in[3 + 2 * i];
        cb[i] = (const float*)d_in[4 + 2 * i];
    }
    const float* hw_w0  = (const float*)d_in[17];
    const float* hw_b0  = (const float*)d_in[18];
    const float* hw_w1  = (const float*)d_in[19];
    const float* hw_b1  = (const float*)d_in[20];
    const float* proj_w = (const float*)d_in[21];
    const float* proj_b = (const float*)d_in[22];
    float* out = (float*)d_out;

    static float *hbuf = nullptr, *pbuf = nullptr, *wtbuf = nullptr;
    static __nv_bfloat16 *hhi, *hlo, *w0hi, *w0lo, *w1hi, *w1lo, *wphi, *wplo;
    static cudaStream_t s2;
    static cudaEvent_t ev_fork, ev_w0, ev_w1, ev_wp, ev_done;
    if (!hbuf) {
        cudaGetSymbolAddress((void**)&hbuf,  g_h);
        cudaGetSymbolAddress((void**)&pbuf,  g_p);
        cudaGetSymbolAddress((void**)&wtbuf, g_wt);
        cudaGetSymbolAddress((void**)&hhi,   g_hhi);
        cudaGetSymbolAddress((void**)&hlo,   g_hlo);
        cudaGetSymbolAddress((void**)&w0hi,  g_w0hi);
        cudaGetSymbolAddress((void**)&w0lo,  g_w0lo);
        cudaGetSymbolAddress((void**)&w1hi,  g_w1hi);
        cudaGetSymbolAddress((void**)&w1lo,  g_w1lo);
        cudaGetSymbolAddress((void**)&wphi,  g_wphi);
        cudaGetSymbolAddress((void**)&wplo,  g_wplo);
        cudaFuncSetAttribute(gemm_f3,
                             cudaFuncAttributeMaxDynamicSharedMemorySize,
                             F_DSMEM);
        cudaStreamCreateWithFlags(&s2, cudaStreamNonBlocking);
        cudaEventCreateWithFlags(&ev_fork, cudaEventDisableTiming);
        cudaEventCreateWithFlags(&ev_w0,   cudaEventDisableTiming);
        cudaEventCreateWithFlags(&ev_w1,   cudaEventDisableTiming);
        cudaEventCreateWithFlags(&ev_wp,   cudaEventDisableTiming);
        cudaEventCreateWithFlags(&ev_done, cudaEventDisableTiming);
    }

    dim3 blk(256);
    const int nW  = 2 * NFILT * NFILT;
    const int nWP = PROJ * NFILT;
    auto cvb = [](int n) { return (n / 4 + 255) / 256; };

    dim3 grid_hwH(2 * NFILT / 64, HALF / 128);   // (64, 16) per half
    dim3 grid_prH(PROJ / 64, HALF / 128);        // (8, 16) per half
    const int hwTotH    = HALF * (NFILT / 4);
    const int hwBlocksH = (hwTotH + 255) / 256;

    const size_t hOffB = (size_t)HALF * NFILT;
    const size_t pOffB = (size_t)HALF * 2 * NFILT;

    // idx 0 (main): transpose
    transpose_all<<<(197120 + 255) / 256, blk>>>(cw[0], cw[1], cw[2], cw[3],
                                                 cw[4], cw[5], cw[6], wtbuf);
    cudaEventRecord(ev_fork, 0);
    cudaStreamWaitEvent(s2, ev_fork, 0);

    // idx 1-2 (s2): w0 + w1 splits
    cvt_split<<<cvb(nW), blk, 0, s2>>>(hw_w0, w0hi, w0lo, nW / 4);
    cudaEventRecord(ev_w0, s2);
    cvt_split<<<cvb(nW), blk, 0, s2>>>(hw_w1, w1hi, w1lo, nW / 4);
    cudaEventRecord(ev_w1, s2);

    // idx 3 (main): conv_A  <-- ncu-profiled slot
    conv_kernel<<<HALF, 256>>>(chars, emb, wtbuf,
                               cb[0], cb[1], cb[2], cb[3], cb[4], cb[5], cb[6],
                               hbuf, hhi, hlo, 0);

    // idx 4 (s2): wp split
    cvt_split<<<cvb(nWP), blk, 0, s2>>>(proj_w, wphi, wplo, nWP / 4);
    cudaEventRecord(ev_wp, s2);

    // idx 5 (s2): conv_B
    conv_kernel<<<HALF, 256, 0, s2>>>(chars, emb, wtbuf,
                                      cb[0], cb[1], cb[2], cb[3], cb[4], cb[5],
                                      cb[6], hbuf, hhi, hlo, HALF);

    // main: chain A
    cudaStreamWaitEvent(0, ev_w0, 0);
    gemm_f3<<<grid_hwH, blk, F_DSMEM>>>(hhi, hlo, w0hi, w0lo, hw_b0,
                                        pbuf, 2 * NFILT, 0);
    highway_kernel<<<hwBlocksH, blk>>>(pbuf, hbuf, hhi, hlo, hwTotH);
    cudaStreamWaitEvent(0, ev_w1, 0);
    gemm_f3<<<grid_hwH, blk, F_DSMEM>>>(hhi, hlo, w1hi, w1lo, hw_b1,
                                        pbuf, 2 * NFILT, 0);
    highway_kernel<<<hwBlocksH, blk>>>(pbuf, hbuf, hhi, hlo, hwTotH);
    cudaStreamWaitEvent(0, ev_wp, 0);
    gemm_f3<<<grid_prH, blk, F_DSMEM>>>(hhi, hlo, wphi, wplo, proj_b,
                                        out, PROJ, 0);

    // s2: chain B
    gemm_f3<<<grid_hwH, blk, F_DSMEM, s2>>>(hhi, hlo, w0hi, w0lo, hw_b0,
                                            pbuf, 2 * NFILT, HALF / 128);
    highway_kernel<<<hwBlocksH, blk, 0, s2>>>(pbuf + pOffB, hbuf + hOffB,
                                              hhi + hOffB, hlo + hOffB, hwTotH);
    gemm_f3<<<grid_hwH, blk, F_DSMEM, s2>>>(hhi, hlo, w1hi, w1lo, hw_b1,
                                            pbuf, 2 * NFILT, HALF / 128);
    highway_kernel<<<hwBlocksH, blk, 0, s2>>>(pbuf + pOffB, hbuf + hOffB,
                                              hhi + hOffB, hlo + hOffB, hwTotH);
    gemm_f3<<<grid_prH, blk, F_DSMEM, s2>>>(hhi, hlo, wphi, wplo, proj_b,
                                            out, PROJ, HALF / 128);

    cudaEventRecord(ev_done, s2);
    cudaStreamWaitEvent(0, ev_done, 0);
}